// round 14
// baseline (speedup 1.0000x reference)
#include <cuda_runtime.h>
#include <cuda_bf16.h>
#include <math.h>
#include <stdint.h>

// ---------------- problem dims ----------------
#define BATCH   8
#define CDIM    256
#define INNER   512
#define NHEADS  8
#define DHEAD   64
#define HQ      96
#define WQ      96
#define NPIX    (HQ*WQ)     // 9216
#define HC      64
#define WC      64
#define CPIX    (HC*WC)     // 4096
#define BH      (BATCH*NHEADS) // 64
#define NKV     64          // 8x8 pruned
#define EPS     1e-5f
#define NPB     (NPIX/64)   // 144 probe partial blocks per bh

// ---------------- scratch (static device memory; no allocs) ----------------
__device__ float  g_q    [BATCH*INNER*NPIX];   // q projection [bh][d][px]
__device__ float  g_k    [BATCH*INNER*CPIX];   // k projection [bh][d][px]
__device__ float  g_obuf [BATCH*CDIM*NPIX];
__device__ float  g_qinv [BH*NPIX];
__device__ float  g_kinv [BH*CPIX];
__device__ float  g_probe_part[BH*NPB*DHEAD];
__device__ float  g_probe[BH*DHEAD];
__device__ float  g_rowsum[BH*DHEAD*HC];
__device__ float  g_colsum[BH*DHEAD*WC];
__device__ int    g_topidx[BH*NKV];
__device__ float2 g_ctx_stat[BATCH*CPIX];
__device__ float2 g_qs_stat [BATCH*NPIX];
__device__ __nv_bfloat16 g_kh[BH*NKV*DHEAD], g_kl[BH*NKV*DHEAD];  // [j][d]
__device__ __nv_bfloat16 g_vh[BH*NKV*DHEAD], g_vl[BH*NKV*DHEAD];  // [d][j]
// pre-split weights (bf16 hi/lo)
__device__ __nv_bfloat16 g_wq_h [INNER*CDIM], g_wq_l [INNER*CDIM];
__device__ __nv_bfloat16 g_wk_h [INNER*CDIM], g_wk_l [INNER*CDIM];
__device__ __nv_bfloat16 g_wo_h [CDIM*INNER], g_wo_l [CDIM*INNER];
// attention output bf16 hi/lo [bh][d][px]
__device__ __nv_bfloat16 g_ah[BATCH*INNER*NPIX], g_al[BATCH*INNER*NPIX];

// ---------------- helpers ----------------
__device__ __forceinline__ uint32_t smem_u32(const void* p) {
    uint32_t a;
    asm("{ .reg .u64 t; cvta.to.shared.u64 t, %1; cvt.u32.u64 %0, t; }" : "=r"(a) : "l"(p));
    return a;
}
__device__ __forceinline__ unsigned short bf_bits(__nv_bfloat16 h) {
    return *reinterpret_cast<unsigned short*>(&h);
}
__device__ __forceinline__ void split1(float v, __nv_bfloat16& h, __nv_bfloat16& l) {
    h = __float2bfloat16(v);
    l = __float2bfloat16(v - __bfloat162float(h));
}
__device__ __forceinline__ void split2(float a, float b, uint32_t& hi, uint32_t& lo) {
    __nv_bfloat16 ha, la, hb, lb;
    split1(a, ha, la); split1(b, hb, lb);
    hi = (uint32_t)bf_bits(ha) | ((uint32_t)bf_bits(hb) << 16);
    lo = (uint32_t)bf_bits(la) | ((uint32_t)bf_bits(lb) << 16);
}
__device__ __forceinline__ void mma_bf16(float* c, const uint32_t* a, const uint32_t* b) {
    asm volatile(
        "mma.sync.aligned.m16n8k16.row.col.f32.bf16.bf16.f32 "
        "{%0,%1,%2,%3}, {%4,%5,%6,%7}, {%8,%9}, {%0,%1,%2,%3};\n"
        : "+f"(c[0]), "+f"(c[1]), "+f"(c[2]), "+f"(c[3])
        : "r"(a[0]), "r"(a[1]), "r"(a[2]), "r"(a[3]), "r"(b[0]), "r"(b[1]));
}
__device__ __forceinline__ void ldsm_x4(uint32_t* r, uint32_t addr) {
    asm volatile("ldmatrix.sync.aligned.m8n8.x4.shared.b16 {%0,%1,%2,%3}, [%4];"
        : "=r"(r[0]), "=r"(r[1]), "=r"(r[2]), "=r"(r[3]) : "r"(addr));
}
__device__ __forceinline__ void ldsm_x4_t(uint32_t* r, uint32_t addr) {
    asm volatile("ldmatrix.sync.aligned.m8n8.x4.trans.shared.b16 {%0,%1,%2,%3}, [%4];"
        : "=r"(r[0]), "=r"(r[1]), "=r"(r[2]), "=r"(r[3]) : "r"(addr));
}

// row stride for bf16 tiles: 72 elems = 144 B (16B-aligned, conflict-free LDSM)
#define RS   72
#define RSB  144

// ---------------- weight hi/lo split (runs once, tiny) ----------------
__global__ void split_w_k(const float* __restrict__ src, __nv_bfloat16* __restrict__ dh,
                          __nv_bfloat16* __restrict__ dl, int n) {
    int i = blockIdx.x*256 + threadIdx.x;
    if (i*4 < n) {
        float4 v = *(const float4*)&src[i*4];
        uint32_t h01, l01, h23, l23;
        split2(v.x, v.y, h01, l01);
        split2(v.z, v.w, h23, l23);
        *(uint2*)&dh[i*4] = make_uint2(h01, h23);
        *(uint2*)&dl[i*4] = make_uint2(l01, l23);
    }
}

// ---------------- per-pixel layernorm stats (float4 + c-split-4) ----------------
__global__ void stat_k(const float* __restrict__ x, float2* __restrict__ st, int HW) {
    int tid = threadIdx.x;
    int cs = tid & 3, pg = blockIdx.x*64 + (tid >> 2);
    int b  = blockIdx.y;
    const float4* xb = (const float4*)(x + (size_t)b*CDIM*HW) + pg;
    int c0 = cs*64, hw4 = HW >> 2;
    float4 s = {0,0,0,0}, s2 = {0,0,0,0};
    #pragma unroll 16
    for (int i = 0; i < 64; i++) {
        float4 v = xb[(size_t)(c0+i)*hw4];
        s.x += v.x; s.y += v.y; s.z += v.z; s.w += v.w;
        s2.x += v.x*v.x; s2.y += v.y*v.y; s2.z += v.z*v.z; s2.w += v.w*v.w;
    }
    #pragma unroll
    for (int off = 1; off <= 2; off <<= 1) {
        s.x += __shfl_xor_sync(~0u, s.x, off);  s.y += __shfl_xor_sync(~0u, s.y, off);
        s.z += __shfl_xor_sync(~0u, s.z, off);  s.w += __shfl_xor_sync(~0u, s.w, off);
        s2.x += __shfl_xor_sync(~0u, s2.x, off); s2.y += __shfl_xor_sync(~0u, s2.y, off);
        s2.z += __shfl_xor_sync(~0u, s2.z, off); s2.w += __shfl_xor_sync(~0u, s2.w, off);
    }
    if (cs == 0) {
        float m0 = s.x*(1.f/CDIM), m1 = s.y*(1.f/CDIM), m2 = s.z*(1.f/CDIM), m3 = s.w*(1.f/CDIM);
        float r0 = rsqrtf(s2.x*(1.f/CDIM) - m0*m0 + EPS);
        float r1 = rsqrtf(s2.y*(1.f/CDIM) - m1*m1 + EPS);
        float r2 = rsqrtf(s2.z*(1.f/CDIM) - m2*m2 + EPS);
        float r3 = rsqrtf(s2.w*(1.f/CDIM) - m3*m3 + EPS);
        float4* dst = (float4*)&st[(size_t)b*HW + pg*4];
        dst[0] = make_float4(m0, r0, m1, r1);
        dst[1] = make_float4(m2, r2, m3, r3);
    }
}

// ---------------- HMMA split GEMM (R13 structure) + fused inv/probe epilogue ----------------
// X source: if Xbh != null, pre-split bf16 (pure-copy staging); else fp32 (+opt norm).
// mode 0: plain; mode 1: q-proj (qinv + probe partials); mode 2: k-proj (kinv)
#define A_TERM 18432                      // 128*RSB
#define B_TERM 9216                       // 64*RSB
#define GEMM_SMEM (2*A_TERM + 2*B_TERM)   // 55296
__global__ void __launch_bounds__(256, 2)
hmma_gemm_k(const __nv_bfloat16* __restrict__ Wh, const __nv_bfloat16* __restrict__ Wl,
            const float* __restrict__ X,
            const __nv_bfloat16* __restrict__ Xbh, const __nv_bfloat16* __restrict__ Xbl,
            const float2* __restrict__ stat, const float* __restrict__ gvec,
            const float* __restrict__ bvec, float* __restrict__ C,
            int M, int N, int K, long strideX, long strideC,
            int mode, float* __restrict__ auxinv, float* __restrict__ ppart) {
    extern __shared__ char smem[];
    char* As0 = smem;
    char* As1 = smem + A_TERM;
    char* Bs0 = smem + 2*A_TERM;
    char* Bs1 = smem + 2*A_TERM + B_TERM;
    uint32_t aBase = smem_u32(As0);
    uint32_t bBase = smem_u32(Bs0);

    int tid = threadIdx.x, lane = tid & 31, wid = tid >> 5;
    int wm = wid & 3, wn = wid >> 2;
    int n0 = blockIdx.x * 64, m0 = blockIdx.y * 128;
    const float* Xp = X ? X + (size_t)blockIdx.z * strideX : nullptr;
    const __nv_bfloat16* Xhp = Xbh ? Xbh + (size_t)blockIdx.z * strideX : nullptr;
    const __nv_bfloat16* Xlp = Xbl ? Xbl + (size_t)blockIdx.z * strideX : nullptr;
    float* Cp = C + (size_t)blockIdx.z * strideC;

    uint32_t aLane = (uint32_t)((wm*32 + ((lane>>3)&1)*8 + (lane&7))*RSB + (lane>>4)*16);
    uint32_t bLane = (uint32_t)((((lane>>3)&1)*8 + (lane&7))*RSB + (wn*32 + (lane>>4)*8)*2);

    int ngf = tid & 7;
    float2 st8[8];
    if (stat) {
        const float2* stp = stat + (size_t)blockIdx.z * N + n0 + ngf*8;
        #pragma unroll
        for (int i = 0; i < 8; i++) st8[i] = stp[i];
    }

    float acc[2][4][4];
    #pragma unroll
    for (int i = 0; i < 2; i++)
        #pragma unroll
        for (int j = 0; j < 4; j++)
            #pragma unroll
            for (int l = 0; l < 4; l++) acc[i][j][l] = 0.f;

    int nch = K >> 6;
    for (int ch = 0; ch < nch; ch++) {
        int k0 = ch << 6;
        // stage A: pre-split bf16, pure uint4 copies
        #pragma unroll
        for (int p = 0; p < 4; p++) {
            int idx = tid + p*256;
            int m = idx >> 3, kg = idx & 7;
            size_t go = (size_t)(m0+m)*K + k0 + kg*8;
            *(uint4*)(As0 + m*RSB + kg*16) = *(const uint4*)&Wh[go];
            *(uint4*)(As1 + m*RSB + kg*16) = *(const uint4*)&Wl[go];
        }
        // stage B
        if (Xhp) {
            // pre-split bf16, pure uint4 copies
            #pragma unroll
            for (int p = 0; p < 2; p++) {
                int idx = tid + p*256;
                int k = idx >> 3;
                size_t go = (size_t)(k0+k)*N + n0 + ngf*8;
                *(uint4*)(Bs0 + k*RSB + ngf*16) = *(const uint4*)&Xhp[go];
                *(uint4*)(Bs1 + k*RSB + ngf*16) = *(const uint4*)&Xlp[go];
            }
        } else {
            // raw fp32 X, optional norm, split, natural [k][n]
            #pragma unroll
            for (int p = 0; p < 2; p++) {
                int idx = tid + p*256;
                int k = idx >> 3;
                const float* src = &Xp[(size_t)(k0+k)*N + n0 + ngf*8];
                float4 x0 = *(const float4*)src;
                float4 x1 = *(const float4*)(src + 4);
                if (stat) {
                    float gg = gvec[k0+k], bb = bvec[k0+k];
                    x0.x = (x0.x - st8[0].x)*st8[0].y*gg + bb;
                    x0.y = (x0.y - st8[1].x)*st8[1].y*gg + bb;
                    x0.z = (x0.z - st8[2].x)*st8[2].y*gg + bb;
                    x0.w = (x0.w - st8[3].x)*st8[3].y*gg + bb;
                    x1.x = (x1.x - st8[4].x)*st8[4].y*gg + bb;
                    x1.y = (x1.y - st8[5].x)*st8[5].y*gg + bb;
                    x1.z = (x1.z - st8[6].x)*st8[6].y*gg + bb;
                    x1.w = (x1.w - st8[7].x)*st8[7].y*gg + bb;
                }
                uint32_t h[4], l[4];
                split2(x0.x, x0.y, h[0], l[0]); split2(x0.z, x0.w, h[1], l[1]);
                split2(x1.x, x1.y, h[2], l[2]); split2(x1.z, x1.w, h[3], l[3]);
                *(uint4*)(Bs0 + k*RSB + ngf*16) = make_uint4(h[0], h[1], h[2], h[3]);
                *(uint4*)(Bs1 + k*RSB + ngf*16) = make_uint4(l[0], l[1], l[2], l[3]);
            }
        }
        __syncthreads();

        #pragma unroll
        for (int kk = 0; kk < 4; kk++) {
            uint32_t af[2][2][4], bfr[2][4][2];
            #pragma unroll
            for (int t = 0; t < 2; t++) {
                #pragma unroll
                for (int tm = 0; tm < 2; tm++)
                    ldsm_x4(af[t][tm], aBase + t*A_TERM + tm*16*RSB + kk*32 + aLane);
                #pragma unroll
                for (int pr = 0; pr < 2; pr++) {
                    uint32_t r[4];
                    ldsm_x4_t(r, bBase + t*B_TERM + kk*16*RSB + pr*32 + bLane);
                    bfr[t][pr*2][0]   = r[0]; bfr[t][pr*2][1]   = r[1];
                    bfr[t][pr*2+1][0] = r[2]; bfr[t][pr*2+1][1] = r[3];
                }
            }
            #pragma unroll
            for (int tm = 0; tm < 2; tm++)
                #pragma unroll
                for (int tn = 0; tn < 4; tn++) {
                    mma_bf16(acc[tm][tn], af[0][tm], bfr[0][tn]);
                    mma_bf16(acc[tm][tn], af[0][tm], bfr[1][tn]);
                    mma_bf16(acc[tm][tn], af[1][tm], bfr[0][tn]);
                }
        }
        __syncthreads();
    }

    // store C
    #pragma unroll
    for (int tm = 0; tm < 2; tm++)
        #pragma unroll
        for (int tn = 0; tn < 4; tn++) {
            int r = m0 + wm*32 + tm*16 + (lane >> 2);
            int c = n0 + wn*32 + tn*8 + (lane & 3)*2;
            *(float2*)&Cp[(size_t)r*N + c]     = make_float2(acc[tm][tn][0], acc[tm][tn][1]);
            *(float2*)&Cp[(size_t)(r+8)*N + c] = make_float2(acc[tm][tn][2], acc[tm][tn][3]);
        }

    // ---- fused epilogue: per-pixel inv L2 norm over each head's 64 rows (+probe) ----
    if (mode) {
        float* ssm  = (float*)smem;          // [4 wm][64 c]
        float* invm = ssm + 256;             // [2 head][64 c]
        float* pmm  = invm + 128;            // [128 row][2 wn]
        int lr = lane >> 2, lc = lane & 3;

        #pragma unroll
        for (int tn = 0; tn < 4; tn++) {
            float s0 = 0.f, s1 = 0.f;
            #pragma unroll
            for (int tm = 0; tm < 2; tm++) {
                s0 += acc[tm][tn][0]*acc[tm][tn][0] + acc[tm][tn][2]*acc[tm][tn][2];
                s1 += acc[tm][tn][1]*acc[tm][tn][1] + acc[tm][tn][3]*acc[tm][tn][3];
            }
            #pragma unroll
            for (int off = 4; off <= 16; off <<= 1) {
                s0 += __shfl_xor_sync(~0u, s0, off);
                s1 += __shfl_xor_sync(~0u, s1, off);
            }
            if (lr == 0) {
                int c = wn*32 + tn*8 + lc*2;
                ssm[wm*64 + c]     = s0;
                ssm[wm*64 + c + 1] = s1;
            }
        }
        __syncthreads();
        if (tid < 128) {
            int head = tid >> 6, c = tid & 63;
            float ss = ssm[(head*2)*64 + c] + ssm[(head*2+1)*64 + c];
            float inv = 1.f / fmaxf(sqrtf(ss), 1e-12f);
            invm[head*64 + c] = inv;
            int bh = blockIdx.z*NHEADS + (m0 >> 6) + head;
            auxinv[(size_t)bh*N + n0 + c] = inv;
        }
        __syncthreads();

        if (mode == 1) {
            int headw = wm >> 1;
            float pr[4] = {0.f, 0.f, 0.f, 0.f};
            #pragma unroll
            for (int tn = 0; tn < 4; tn++) {
                int c = wn*32 + tn*8 + lc*2;
                float i0 = invm[headw*64 + c], i1 = invm[headw*64 + c + 1];
                #pragma unroll
                for (int tm = 0; tm < 2; tm++) {
                    pr[tm*2]     += acc[tm][tn][0]*i0 + acc[tm][tn][1]*i1;
                    pr[tm*2 + 1] += acc[tm][tn][2]*i0 + acc[tm][tn][3]*i1;
                }
            }
            #pragma unroll
            for (int off = 1; off <= 2; off <<= 1)
                #pragma unroll
                for (int r = 0; r < 4; r++) pr[r] += __shfl_xor_sync(~0u, pr[r], off);
            if (lc == 0) {
                #pragma unroll
                for (int tm = 0; tm < 2; tm++) {
                    pmm[(wm*32 + tm*16 + lr)*2 + wn]     = pr[tm*2];
                    pmm[(wm*32 + tm*16 + lr + 8)*2 + wn] = pr[tm*2 + 1];
                }
            }
            __syncthreads();
            if (tid < 128) {
                int row = tid, head = row >> 6, d = row & 63;
                float p = pmm[row*2] + pmm[row*2 + 1];
                int bh = blockIdx.z*NHEADS + (m0 >> 6) + head;
                ppart[((size_t)bh*gridDim.x + blockIdx.x)*DHEAD + d] = p;
            }
        }
    }
}

__global__ void probe_reduce_k(const float* __restrict__ part, float* __restrict__ probe) {
    int bh = blockIdx.x, d = threadIdx.x;
    float s = 0.f;
    for (int i = 0; i < NPB; i++) s += part[((size_t)bh*NPB + i)*DHEAD + d];
    probe[bh*DHEAD + d] = s;
}

// ---------------- row/col |k| sums ----------------
__global__ void rowcol_k(const float* __restrict__ k, const float* __restrict__ kinv,
                         float* __restrict__ rowsum, float* __restrict__ colsum) {
    int d = blockIdx.x, bh = blockIdx.y, t = threadIdx.x; // 64 threads
    __shared__ float s[64*65];
    const float* base = k + ((size_t)bh*DHEAD + d)*CPIX;
    const float* inv  = kinv + (size_t)bh*CPIX;
    #pragma unroll 8
    for (int h = 0; h < 64; h++) {
        int px = h*64 + t;
        s[h*65 + t] = fabsf(base[px]) * inv[px];
    }
    __syncthreads();
    float rs = 0.f, cs = 0.f;
    #pragma unroll 8
    for (int w = 0; w < 64; w++) rs += s[t*65 + w];
    #pragma unroll 8
    for (int h = 0; h < 64; h++) cs += s[h*65 + t];
    rowsum[((size_t)bh*DHEAD + d)*HC + t] = rs;
    colsum[((size_t)bh*DHEAD + d)*WC + t] = cs;
}

// ---------------- scores + exact top-8 (first index wins ties) ----------------
__global__ void topk_k(const float* __restrict__ probe, const float* __restrict__ rowsum,
                       const float* __restrict__ colsum, int* __restrict__ topidx) {
    int bh = blockIdx.x, t = threadIdx.x; // 64 threads
    __shared__ float sr[64], sc[64];
    __shared__ int th[8], tw[8];
    float r = 0.f, c = 0.f;
    for (int d = 0; d < DHEAD; d++) {
        float p = probe[bh*DHEAD + d];
        r += p * rowsum[((size_t)bh*DHEAD + d)*HC + t];
        c += p * colsum[((size_t)bh*DHEAD + d)*WC + t];
    }
    sr[t] = r; sc[t] = c;
    __syncthreads();
    if (t == 0) {
        bool used[64];
        for (int i = 0; i < 64; i++) used[i] = false;
        for (int i = 0; i < 8; i++) {
            float best = -1e38f; int bi = 0;
            for (int h = 0; h < 64; h++)
                if (!used[h] && sr[h] > best) { best = sr[h]; bi = h; }
            used[bi] = true; th[i] = bi;
        }
        for (int i = 0; i < 64; i++) used[i] = false;
        for (int i = 0; i < 8; i++) {
            float best = -1e38f; int bi = 0;
            for (int w = 0; w < 64; w++)
                if (!used[w] && sc[w] > best) { best = sc[w]; bi = w; }
            used[bi] = true; tw[i] = bi;
        }
        for (int i = 0; i < 8; i++)
            for (int j = 0; j < 8; j++)
                topidx[bh*NKV + i*8 + j] = th[i]*WC + tw[j];
    }
}

// ---------------- pack: K split [j][d]; V at pruned px split [d][j] ----------------
__global__ void pack_k(const float* __restrict__ k, const float* __restrict__ kinv,
                       const float* __restrict__ ctx_raw, const float2* __restrict__ cstat,
                       const float* __restrict__ cg, const float* __restrict__ cb_,
                       const float* __restrict__ wkv, const int* __restrict__ topidx,
                       __nv_bfloat16* __restrict__ kh, __nv_bfloat16* __restrict__ kl,
                       __nv_bfloat16* __restrict__ vh, __nv_bfloat16* __restrict__ vl) {
    extern __shared__ float ctx_s[];   // [c][j]
    __shared__ int pos[NKV];
    __shared__ float2 stj[NKV];
    int bh = blockIdx.x, b = bh >> 3, h = bh & 7;
    int tid = threadIdx.x;
    if (tid < NKV) {
        int p = topidx[bh*NKV + tid];
        pos[tid] = p;
        stj[tid] = cstat[(size_t)b*CPIX + p];
    }
    __syncthreads();

    int j = tid & 63, c0 = tid >> 6;
    float2 st = stj[j];
    for (int cc = 0; cc < 64; cc++) {
        int c = cc*4 + c0;
        float raw = ctx_raw[((size_t)b*CDIM + c)*CPIX + pos[j]];
        ctx_s[c*64 + j] = (raw - st.x)*st.y*cg[c] + cb_[c];
    }

    #pragma unroll
    for (int i = 0; i < 16; i++) {
        int idx = tid + i*256;
        int jj = idx >> 6, d = idx & 63;
        int p = pos[jj];
        float kv = k[((size_t)bh*DHEAD + d)*CPIX + p] * kinv[(size_t)bh*CPIX + p];
        __nv_bfloat16 hh, ll;
        split1(kv, hh, ll);
        kh[(size_t)bh*NKV*DHEAD + idx] = hh;
        kl[(size_t)bh*NKV*DHEAD + idx] = ll;
    }
    __syncthreads();

    for (int dd = 0; dd < 16; dd++) {
        int d = dd*4 + c0;
        const float* wr = wkv + ((size_t)(INNER + h*DHEAD + d))*CDIM;
        float acc = 0.f;
        #pragma unroll 8
        for (int c = 0; c < CDIM; c++) acc += wr[c] * ctx_s[c*64 + j];
        __nv_bfloat16 hh, ll;
        split1(acc, hh, ll);
        vh[(size_t)bh*NKV*DHEAD + d*64 + j] = hh;
        vl[(size_t)bh*NKV*DHEAD + d*64 + j] = ll;
    }
}

// ---------------- fused HMMA attention: in-register softmax, bf16 hi/lo output ----------------
#define AQ_TERM 18432                     // 128*RSB
#define AK_TERM 9216                      // 64*RSB
#define ATTN_SMEM (2*AQ_TERM + 2*AK_TERM)   // 55296
__global__ void __launch_bounds__(256)
attn_k(const float* __restrict__ qb_all, const float* __restrict__ qinv_all,
       const __nv_bfloat16* __restrict__ kh_all, const __nv_bfloat16* __restrict__ kl_all,
       const __nv_bfloat16* __restrict__ vh_all, const __nv_bfloat16* __restrict__ vl_all,
       __nv_bfloat16* __restrict__ ah_all, __nv_bfloat16* __restrict__ al_all) {
    extern __shared__ char smem[];
    char* Qh = smem;                        // [px][RS]  (later Ph/Pl, then Os)
    char* Ql = smem + AQ_TERM;
    char* Kh = smem + 2*AQ_TERM;            // [j][RS] (later V [d][RS])
    char* Kl = smem + 2*AQ_TERM + AK_TERM;
    __shared__ float qiv[128];
    __shared__ float red[128][2];
    uint32_t qBase = smem_u32(Qh);
    uint32_t kBase = smem_u32(Kh);

    int bh = blockIdx.y;
    int px0 = blockIdx.x * 128;
    int tid = threadIdx.x, lane = tid & 31, wid = tid >> 5;
    int wm = wid & 3, wn = wid >> 2;
    int lr = lane >> 2, lc = lane & 3;

    const float* qb = qb_all + (size_t)bh*DHEAD*NPIX + px0;
    const float* qi = qinv_all + (size_t)bh*NPIX + px0;
    const uint32_t* khp = (const uint32_t*)(kh_all + (size_t)bh*NKV*DHEAD);
    const uint32_t* klp = (const uint32_t*)(kl_all + (size_t)bh*NKV*DHEAD);
    const uint32_t* vhp = (const uint32_t*)(vh_all + (size_t)bh*NKV*DHEAD);
    const uint32_t* vlp = (const uint32_t*)(vl_all + (size_t)bh*NKV*DHEAD);

    uint32_t aLane = (uint32_t)((wm*32 + ((lane>>3)&1)*8 + (lane&7))*RSB + (lane>>4)*16);
    uint32_t bLane = (uint32_t)(((lane>>4)*8 + (lane&7))*RSB + ((lane>>3)&1)*16 + wn*32*RSB);

    if (tid < 128) qiv[tid] = qi[tid];
    for (int i = tid; i < 2048; i += 256) {
        int j = i >> 5, dp = i & 31;
        ((uint32_t*)(Kh + j*RSB))[dp] = khp[i];
        ((uint32_t*)(Kl + j*RSB))[dp] = klp[i];
    }
    __syncthreads();
    #pragma unroll
    for (int it = 0; it < 16; it++) {
        int idx = tid + it*256;
        int p  = (idx & 7) | (((idx >> 5) & 15) << 3);
        int dp = ((idx >> 3) & 3) | ((idx >> 9) << 2);
        float iv = qiv[p];
        float v0 = qb[(size_t)(2*dp)*NPIX + p] * iv;
        float v1 = qb[(size_t)(2*dp+1)*NPIX + p] * iv;
        uint32_t hi, lo;
        split2(v0, v1, hi, lo);
        ((uint32_t*)(Qh + p*RSB))[dp] = hi;
        ((uint32_t*)(Ql + p*RSB))[dp] = lo;
    }
    __syncthreads();

    // QK^T -> acc (registers)
    float acc[2][4][4];
    #pragma unroll
    for (int i = 0; i < 2; i++)
        #pragma unroll
        for (int j = 0; j < 4; j++)
            #pragma unroll
            for (int l = 0; l < 4; l++) acc[i][j][l] = 0.f;
    #pragma unroll
    for (int kk = 0; kk < 4; kk++) {
        uint32_t af[2][2][4], bfr[2][4][2];
        #pragma unroll
        for (int t = 0; t < 2; t++) {
            #pragma unroll
            for (int tm = 0; tm < 2; tm++)
                ldsm_x4(af[t][tm], qBase + t*AQ_TERM + tm*16*RSB + kk*32 + aLane);
            #pragma unroll
            for (int pr = 0; pr < 2; pr++) {
                uint32_t r[4];
                ldsm_x4(r, kBase + t*AK_TERM + pr*16*RSB + kk*32 + bLane);
                bfr[t][pr*2][0]   = r[0]; bfr[t][pr*2][1]   = r[1];
                bfr[t][pr*2+1][0] = r[2]; bfr[t][pr*2+1][1] = r[3];
            }
        }
        #pragma unroll
        for (int tm = 0; tm < 2; tm++)
            #pragma unroll
            for (int tn = 0; tn < 4; tn++) {
                mma_bf16(acc[tm][tn], af[0][tm], bfr[0][tn]);
                mma_bf16(acc[tm][tn], af[0][tm], bfr[1][tn]);
                mma_bf16(acc[tm][tn], af[1][tm], bfr[0][tn]);
            }
    }
    __syncthreads();   // all K/Q smem reads done

    // stage V into K region ([d][RS])
    for (int i = tid; i < 2048; i += 256) {
        int d = i >> 5, jp = i & 31;
        ((uint32_t*)(Kh + d*RSB))[jp] = vhp[i];
        ((uint32_t*)(Kl + d*RSB))[jp] = vlp[i];
    }

    // ---- in-register softmax over j ----
    float mrow[2][2];
    #pragma unroll
    for (int tm = 0; tm < 2; tm++) {
        float m0 = -1e30f, m1 = -1e30f;
        #pragma unroll
        for (int tn = 0; tn < 4; tn++) {
            m0 = fmaxf(m0, fmaxf(acc[tm][tn][0], acc[tm][tn][1]));
            m1 = fmaxf(m1, fmaxf(acc[tm][tn][2], acc[tm][tn][3]));
        }
        #pragma unroll
        for (int off = 1; off <= 2; off <<= 1) {
            m0 = fmaxf(m0, __shfl_xor_sync(~0u, m0, off));
            m1 = fmaxf(m1, __shfl_xor_sync(~0u, m1, off));
        }
        mrow[tm][0] = m0; mrow[tm][1] = m1;
    }
    if (lc == 0) {
        #pragma unroll
        for (int tm = 0; tm < 2; tm++) {
            red[wm*32 + tm*16 + lr][wn]     = mrow[tm][0];
            red[wm*32 + tm*16 + lr + 8][wn] = mrow[tm][1];
        }
    }
    __syncthreads();
    float fm[2][2];
    #pragma unroll
    for (int tm = 0; tm < 2; tm++) {
        fm[tm][0] = fmaxf(red[wm*32 + tm*16 + lr][0],     red[wm*32 + tm*16 + lr][1]);
        fm[tm][1] = fmaxf(red[wm*32 + tm*16 + lr + 8][0], red[wm*32 + tm*16 + lr + 8][1]);
    }
    __syncthreads();
    float srow[2][2] = {{0.f,0.f},{0.f,0.f}};
    #pragma unroll
    for (int tm = 0; tm < 2; tm++)
        #pragma unroll
        for (int tn = 0; tn < 4; tn++) {
            acc[tm][tn][0] = expf(acc[tm][tn][0] - fm[tm][0]);
            acc[tm][tn][1] = expf(acc[tm][tn][1] - fm[tm][0]);
            acc[tm][tn][2] = expf(acc[tm][tn][2] - fm[tm][1]);
            acc[tm][tn][3] = expf(acc[tm][tn][3] - fm[tm][1]);
            srow[tm][0] += acc[tm][tn][0] + acc[tm][tn][1];
            srow[tm][1] += acc[tm][tn][2] + acc[tm][tn][3];
        }
    #pragma unroll
    for (int tm = 0; tm < 2; tm++)
        #pragma unroll
        for (int off = 1; off <= 2; off <<= 1) {
            srow[tm][0] += __shfl_xor_sync(~0u, srow[tm][0], off);
            srow[tm][1] += __shfl_xor_sync(~0u, srow[tm][1], off);
        }
    if (lc == 0) {
        #pragma unroll
        for (int tm = 0; tm < 2; tm++) {
            red[wm*32 + tm*16 + lr][wn]     = srow[tm][0];
            red[wm*32 + tm*16 + lr + 8][wn] = srow[tm][1];
        }
    }
    __syncthreads();
    float fs[2][2];
    #pragma unroll
    for (int tm = 0; tm < 2; tm++) {
        fs[tm][0] = 1.f / (red[wm*32 + tm*16 + lr][0]     + red[wm*32 + tm*16 + lr][1]);
        fs[tm][1] = 1.f / (red[wm*32 + tm*16 + lr + 8][0] + red[wm*32 + tm*16 + lr + 8][1]);
    }

    // scale + split directly into Qh/Ql as P tiles [r][j]
    #pragma unroll
    for (int tm = 0; tm < 2; tm++)
        #pragma unroll
        for (int tn = 0; tn < 4; tn++) {
            int r1 = wm*32 + tm*16 + lr;
            int cw = wn*16 + tn*4 + lc;   // uint32 index = col/2
            float p0 = acc[tm][tn][0] * fs[tm][0];
            float p1 = acc[tm][tn][1] * fs[tm][0];
            float p2 = acc[tm][tn][2] * fs[tm][1];
            float p3 = acc[tm][tn][3] * fs[tm][1];
            uint32_t hi, lo;
            split2(p0, p1, hi, lo);
            ((uint32_t*)(Qh + r1*RSB))[cw] = hi;
            ((uint32_t*)(Ql + r1*RSB))[cw] = lo;
            split2(p2, p3, hi, lo);
            ((uint32_t*)(Qh + (r1+8)*RSB))[cw] = hi;
            ((uint32_t*)(Ql + (r1+8)*RSB))[cw] = lo;
        }
    __syncthreads();

    // P @ V -> out[px][d]
    {
        float acc2[2][4][4];
        #pragma unroll
        for (int i = 0; i < 2; i++)
            #pragma unroll
            for (int j = 0; j < 4; j++)
                #pragma unroll
                for (int l = 0; l < 4; l++) acc2[i][j][l] = 0.f;
        #pragma unroll
        for (int kk = 0; kk < 4; kk++) {
            uint32_t af[2][2][4], bfr[2][4][2];
            #pragma unroll
            for (int t = 0; t < 2; t++) {
                #pragma unroll
                for (int tm = 0; tm < 2; tm++)
                    ldsm_x4(af[t][tm], qBase + t*AQ_TERM + tm*16*RSB + kk*32 + aLane);
                #pragma unroll
                for (int pr = 0; pr < 2; pr++) {
                    uint32_t r[4];
                    ldsm_x4(r, kBase + t*AK_TERM + pr*16*RSB + kk*32 + bLane);
                    bfr[t][pr*2][0]   = r[0]; bfr[t][pr*2][1]   = r[1];
                    bfr[t][pr*2+1][0] = r[2]; bfr[t][pr*2+1][1] = r[3];
                }
            }
            #pragma unroll
            for (int tm = 0; tm < 2; tm++)
                #pragma unroll
                for (int tn = 0; tn < 4; tn++) {
                    mma_bf16(acc2[tm][tn], af[0][tm], bfr[0][tn]);
                    mma_bf16(acc2[tm][tn], af[0][tm], bfr[1][tn]);
                    mma_bf16(acc2[tm][tn], af[1][tm], bfr[0][tn]);
                }
        }
        __syncthreads();   // P/V reads done; reuse Qh/Ql region as Os [64][132] fp32
        float* Os = (float*)Qh;
        #pragma unroll
        for (int tm = 0; tm < 2; tm++)
            #pragma unroll
            for (int tn = 0; tn < 4; tn++) {
                int r = wm*32 + tm*16 + lr;
                int c = wn*32 + tn*8 + lc*2;
                Os[c*132 + r]       = acc2[tm][tn][0];
                Os[(c+1)*132 + r]   = acc2[tm][tn][1];
                Os[c*132 + r + 8]   = acc2[tm][tn][2];
                Os[(c+1)*132 + r+8] = acc2[tm][tn][3];
            }
        __syncthreads();
        // write bf16 hi/lo [d][px]
        size_t base = (size_t)bh*DHEAD*NPIX + px0;
        for (int i = tid; i < 4096; i += 256) {
            int d = i >> 6, pp = i & 63;
            float v0 = Os[d*132 + 2*pp];
            float v1 = Os[d*132 + 2*pp + 1];
            uint32_t hi, lo;
            split2(v0, v1, hi, lo);
            *(uint32_t*)(ah_all + base + (size_t)d*NPIX + 2*pp) = hi;
            *(uint32_t*)(al_all + base + (size_t)d*NPIX + 2*pp) = lo;
        }
    }
}

// ---------------- final (float4 + c-split-4): channorm(obuf)*gamma + residual ----------------
__global__ void final_k(const float* __restrict__ x, const float* __restrict__ g,
                        const float* __restrict__ bb, const float* __restrict__ gamma,
                        const float* __restrict__ resid, float* __restrict__ y) {
    int tid = threadIdx.x;
    int cs = tid & 3, pg = blockIdx.x*64 + (tid >> 2);
    int b  = blockIdx.y;
    const float4* xb = (const float4*)(x + (size_t)b*CDIM*NPIX) + pg;
    const float4* rb = (const float4*)(resid + (size_t)b*CDIM*NPIX) + pg;
    float4* yb = (float4*)(y + (size_t)b*CDIM*NPIX) + pg;
    int c0 = cs*64, hw4 = NPIX >> 2;
    float4 s = {0,0,0,0}, s2 = {0,0,0,0};
    #pragma unroll 16
    for (int i = 0; i < 64; i++) {
        float4 v = xb[(size_t)(c0+i)*hw4];
        s.x += v.x; s.y += v.y; s.z += v.z; s.w += v.w;
        s2.x += v.x*v.x; s2.y += v.y*v.y; s2.z += v.z*v.z; s2.w += v.w*v.w;
    }
    #pragma unroll
    for (int off = 1; off <= 2; off <<= 1) {
        s.x += __shfl_xor_sync(~0u, s.x, off);  s.y += __shfl_xor_sync(~0u, s.y, off);
        s.z += __shfl_xor_sync(~0u, s.z, off);  s.w += __shfl_xor_sync(~0u, s.w, off);
        s2.x += __shfl_xor_sync(~0u, s2.x, off); s2.y += __shfl_xor_sync(~0u, s2.y, off);
        s2.z += __shfl_xor_sync(~0u, s2.z, off); s2.w += __shfl_xor_sync(~0u, s2.w, off);
    }
    float m0 = s.x*(1.f/CDIM), m1 = s.y*(1.f/CDIM), m2 = s.z*(1.f/CDIM), m3 = s.w*(1.f/CDIM);
    float r0 = rsqrtf(s2.x*(1.f/CDIM) - m0*m0 + EPS);
    float r1 = rsqrtf(s2.y*(1.f/CDIM) - m1*m1 + EPS);
    float r2 = rsqrtf(s2.z*(1.f/CDIM) - m2*m2 + EPS);
    float r3 = rsqrtf(s2.w*(1.f/CDIM) - m3*m3 + EPS);
    float gm = gamma[0];
    #pragma unroll 8
    for (int i = 0; i < 64; i++) {
        int c = c0 + i;
        float4 v = xb[(size_t)c*hw4];
        float4 rr = rb[(size_t)c*hw4];
        float gg = g[c], bv = bb[c];
        float4 o;
        o.x = gm*((v.x - m0)*r0*gg + bv) + rr.x;
        o.y = gm*((v.y - m1)*r1*gg + bv) + rr.y;
        o.z = gm*((v.z - m2)*r2*gg + bv) + rr.z;
        o.w = gm*((v.w - m3)*r3*gg + bv) + rr.w;
        yb[(size_t)c*hw4] = o;
    }
}

// ---------------- launch ----------------
extern "C" void kernel_launch(void* const* d_in, const int* in_sizes, int n_in,
                              void* d_out, int out_size) {
    const float* query_source = (const float*)d_in[0];
    const float* context      = (const float*)d_in[1];
    const float* qs_g  = (const float*)d_in[2];
    const float* qs_b  = (const float*)d_in[3];
    const float* ctx_g = (const float*)d_in[4];
    const float* ctx_b = (const float*)d_in[5];
    const float* out_g = (const float*)d_in[6];
    const float* out_b = (const float*)d_in[7];
    const float* w_q   = (const float*)d_in[8];
    const float* w_kv  = (const float*)d_in[9];
    const float* w_out = (const float*)d_in[10];
    const float* gamma = (const float*)d_in[11];
    float* out = (float*)d_out;

    float *qb, *kb, *obuf, *qinv, *kinv, *ppart, *probe, *rowsum, *colsum;
    int* topidx;
    float2 *cstat, *qstat;
    __nv_bfloat16 *kh, *kl, *vh, *vl, *wqh, *wql, *wkh, *wkl, *woh, *wol, *ah, *al;
    cudaGetSymbolAddress((void**)&qb,    g_q);
    cudaGetSymbolAddress((void**)&kb,    g_k);
    cudaGetSymbolAddress((void**)&obuf,  g_obuf);
    cudaGetSymbolAddress((void**)&qinv,  g_qinv);
    cudaGetSymbolAddress((void**)&kinv,  g_kinv);
    cudaGetSymbolAddress((void**)&ppart, g_probe_part);
    cudaGetSymbolAddress((void**)&probe, g_probe);
    cudaGetSymbolAddress((void**)&rowsum,g_rowsum);
    cudaGetSymbolAddress((void**)&colsum,g_colsum);
    cudaGetSymbolAddress((void**)&topidx,g_topidx);
    cudaGetSymbolAddress((void**)&cstat, g_ctx_stat);
    cudaGetSymbolAddress((void**)&qstat, g_qs_stat);
    cudaGetSymbolAddress((void**)&kh,    g_kh);
    cudaGetSymbolAddress((void**)&kl,    g_kl);
    cudaGetSymbolAddress((void**)&vh,    g_vh);
    cudaGetSymbolAddress((void**)&vl,    g_vl);
    cudaGetSymbolAddress((void**)&wqh,   g_wq_h);
    cudaGetSymbolAddress((void**)&wql,   g_wq_l);
    cudaGetSymbolAddress((void**)&wkh,   g_wk_h);
    cudaGetSymbolAddress((void**)&wkl,   g_wk_l);
    cudaGetSymbolAddress((void**)&woh,   g_wo_h);
    cudaGetSymbolAddress((void**)&wol,   g_wo_l);
    cudaGetSymbolAddress((void**)&ah,    g_ah);
    cudaGetSymbolAddress((void**)&al,    g_al);

    cudaFuncSetAttribute(hmma_gemm_k, cudaFuncAttributeMaxDynamicSharedMemorySize, GEMM_SMEM);
    cudaFuncSetAttribute(attn_k, cudaFuncAttributeMaxDynamicSharedMemorySize, ATTN_SMEM);
    cudaFuncSetAttribute(pack_k, cudaFuncAttributeMaxDynamicSharedMemorySize, 256*64*4);

    // 0) weight splits (tiny)
    split_w_k<<<(INNER*CDIM/4 + 255)/256, 256>>>(w_q,   wqh, wql, INNER*CDIM);
    split_w_k<<<(INNER*CDIM/4 + 255)/256, 256>>>(w_kv,  wkh, wkl, INNER*CDIM);  // K half
    split_w_k<<<(CDIM*INNER/4 + 255)/256, 256>>>(w_out, woh, wol, CDIM*INNER);

    // 1) per-pixel layernorm stats
    stat_k<<<dim3(CPIX/256, BATCH), 256>>>(context, cstat, CPIX);
    stat_k<<<dim3(NPIX/256, BATCH), 256>>>(query_source, qstat, NPIX);

    // 2) projections with fused inv/probe epilogues (fp32 X + fused norm)
    hmma_gemm_k<<<dim3(CPIX/64, INNER/128, BATCH), 256, GEMM_SMEM>>>(
        wkh, wkl, context, nullptr, nullptr, cstat, ctx_g, ctx_b, kb, INNER, CPIX, CDIM,
        (long)CDIM*CPIX, (long)INNER*CPIX, 2, kinv, nullptr);
    hmma_gemm_k<<<dim3(NPIX/64, INNER/128, BATCH), 256, GEMM_SMEM>>>(
        wqh, wql, query_source, nullptr, nullptr, qstat, qs_g, qs_b, qb, INNER, NPIX, CDIM,
        (long)CDIM*NPIX, (long)INNER*NPIX, 1, qinv, ppart);

    // 3) probe + pruning scores
    probe_reduce_k<<<BH, DHEAD>>>(ppart, probe);
    rowcol_k<<<dim3(DHEAD, BH), 64>>>(kb, kinv, rowsum, colsum);
    topk_k<<<BH, 64>>>(probe, rowsum, colsum, topidx);

    // 4) pack pruned K (split) + compute pruned V (split, transposed)
    pack_k<<<BH, 256, 256*64*4>>>(kb, kinv, context, cstat, ctx_g, ctx_b,
                                  w_kv, topidx, kh, kl, vh, vl);

    // 5) fused HMMA attention (in-register softmax; bf16 hi/lo output)
    attn_k<<<dim3(NPIX/128, BH), 256, ATTN_SMEM>>>(qb, qinv, kh, kl, vh, vl, ah, al);

    // 6) output projection (bf16 X, pure-copy staging)
    hmma_gemm_k<<<dim3(NPIX/64, CDIM/128, BATCH), 256, GEMM_SMEM>>>(
        woh, wol, nullptr, ah, al, nullptr, nullptr, nullptr, obuf, CDIM, NPIX, INNER,
        (long)INNER*NPIX, (long)CDIM*NPIX, 0, nullptr, nullptr);

    // 7) final norm + gamma + residual
    final_k<<<dim3(NPIX/256, BATCH), 256>>>(obuf, out_g, out_b, gamma, query_source, out);
}

// round 15
// speedup vs baseline: 1.0206x; 1.0206x over previous
#include <cuda_runtime.h>
#include <cuda_bf16.h>
#include <math.h>
#include <stdint.h>

// ---------------- problem dims ----------------
#define BATCH   8
#define CDIM    256
#define INNER   512
#define NHEADS  8
#define DHEAD   64
#define HQ      96
#define WQ      96
#define NPIX    (HQ*WQ)     // 9216
#define HC      64
#define WC      64
#define CPIX    (HC*WC)     // 4096
#define BH      (BATCH*NHEADS) // 64
#define NKV     64          // 8x8 pruned
#define EPS     1e-5f
#define NPB     (NPIX/64)   // 144 probe partial blocks per bh

// ---------------- scratch (static device memory; no allocs) ----------------
__device__ float  g_q    [BATCH*INNER*NPIX];   // q projection [bh][d][px]
__device__ float  g_k    [BATCH*INNER*CPIX];   // k projection [bh][d][px]
__device__ float  g_attno[BATCH*INNER*NPIX];   // attention out [bh][d][px]
__device__ float  g_obuf [BATCH*CDIM*NPIX];
__device__ float  g_qinv [BH*NPIX];
__device__ float  g_kinv [BH*CPIX];
__device__ float  g_probe_part[BH*NPB*DHEAD];
__device__ float  g_probe[BH*DHEAD];
__device__ float  g_rowsum[BH*DHEAD*HC];
__device__ float  g_colsum[BH*DHEAD*WC];
__device__ int    g_topidx[BH*NKV];
__device__ float2 g_ctx_stat[BATCH*CPIX];
__device__ float2 g_qs_stat [BATCH*NPIX];
__device__ __nv_bfloat16 g_kh[BH*NKV*DHEAD], g_kl[BH*NKV*DHEAD];  // [j][d]
__device__ __nv_bfloat16 g_vh[BH*NKV*DHEAD], g_vl[BH*NKV*DHEAD];  // [d][j]
// pre-split weights (bf16 hi/lo)
__device__ __nv_bfloat16 g_wq_h [INNER*CDIM], g_wq_l [INNER*CDIM];
__device__ __nv_bfloat16 g_wk_h [INNER*CDIM], g_wk_l [INNER*CDIM];
__device__ __nv_bfloat16 g_wo_h [CDIM*INNER], g_wo_l [CDIM*INNER];

// ---------------- helpers ----------------
__device__ __forceinline__ uint32_t smem_u32(const void* p) {
    uint32_t a;
    asm("{ .reg .u64 t; cvta.to.shared.u64 t, %1; cvt.u32.u64 %0, t; }" : "=r"(a) : "l"(p));
    return a;
}
__device__ __forceinline__ unsigned short bf_bits(__nv_bfloat16 h) {
    return *reinterpret_cast<unsigned short*>(&h);
}
__device__ __forceinline__ void split1(float v, __nv_bfloat16& h, __nv_bfloat16& l) {
    h = __float2bfloat16(v);
    l = __float2bfloat16(v - __bfloat162float(h));
}
__device__ __forceinline__ void split2(float a, float b, uint32_t& hi, uint32_t& lo) {
    __nv_bfloat16 ha, la, hb, lb;
    split1(a, ha, la); split1(b, hb, lb);
    hi = (uint32_t)bf_bits(ha) | ((uint32_t)bf_bits(hb) << 16);
    lo = (uint32_t)bf_bits(la) | ((uint32_t)bf_bits(lb) << 16);
}
__device__ __forceinline__ void mma_bf16(float* c, const uint32_t* a, const uint32_t* b) {
    asm volatile(
        "mma.sync.aligned.m16n8k16.row.col.f32.bf16.bf16.f32 "
        "{%0,%1,%2,%3}, {%4,%5,%6,%7}, {%8,%9}, {%0,%1,%2,%3};\n"
        : "+f"(c[0]), "+f"(c[1]), "+f"(c[2]), "+f"(c[3])
        : "r"(a[0]), "r"(a[1]), "r"(a[2]), "r"(a[3]), "r"(b[0]), "r"(b[1]));
}
__device__ __forceinline__ void ldsm_x4(uint32_t* r, uint32_t addr) {
    asm volatile("ldmatrix.sync.aligned.m8n8.x4.shared.b16 {%0,%1,%2,%3}, [%4];"
        : "=r"(r[0]), "=r"(r[1]), "=r"(r[2]), "=r"(r[3]) : "r"(addr));
}
__device__ __forceinline__ void ldsm_x4_t(uint32_t* r, uint32_t addr) {
    asm volatile("ldmatrix.sync.aligned.m8n8.x4.trans.shared.b16 {%0,%1,%2,%3}, [%4];"
        : "=r"(r[0]), "=r"(r[1]), "=r"(r[2]), "=r"(r[3]) : "r"(addr));
}

// row stride for bf16 tiles: 72 elems = 144 B (16B-aligned, conflict-free LDSM)
#define RS   72
#define RSB  144

// ---------------- weight hi/lo split (runs once, tiny) ----------------
__global__ void split_w_k(const float* __restrict__ src, __nv_bfloat16* __restrict__ dh,
                          __nv_bfloat16* __restrict__ dl, int n) {
    int i = blockIdx.x*256 + threadIdx.x;
    if (i*4 < n) {
        float4 v = *(const float4*)&src[i*4];
        uint32_t h01, l01, h23, l23;
        split2(v.x, v.y, h01, l01);
        split2(v.z, v.w, h23, l23);
        *(uint2*)&dh[i*4] = make_uint2(h01, h23);
        *(uint2*)&dl[i*4] = make_uint2(l01, l23);
    }
}

// ---------------- per-pixel layernorm stats (float4 + c-split-8, 128 px/block) ----------------
__global__ void stat_k(const float* __restrict__ x, float2* __restrict__ st, int HW) {
    int tid = threadIdx.x;
    int cs = tid & 7, pg = blockIdx.x*32 + (tid >> 3);
    int b  = blockIdx.y;
    const float4* xb = (const float4*)(x + (size_t)b*CDIM*HW) + pg;
    int c0 = cs*32, hw4 = HW >> 2;
    float4 s = {0,0,0,0}, s2 = {0,0,0,0};
    #pragma unroll 16
    for (int i = 0; i < 32; i++) {
        float4 v = xb[(size_t)(c0+i)*hw4];
        s.x += v.x; s.y += v.y; s.z += v.z; s.w += v.w;
        s2.x += v.x*v.x; s2.y += v.y*v.y; s2.z += v.z*v.z; s2.w += v.w*v.w;
    }
    #pragma unroll
    for (int off = 1; off <= 4; off <<= 1) {
        s.x += __shfl_xor_sync(~0u, s.x, off);  s.y += __shfl_xor_sync(~0u, s.y, off);
        s.z += __shfl_xor_sync(~0u, s.z, off);  s.w += __shfl_xor_sync(~0u, s.w, off);
        s2.x += __shfl_xor_sync(~0u, s2.x, off); s2.y += __shfl_xor_sync(~0u, s2.y, off);
        s2.z += __shfl_xor_sync(~0u, s2.z, off); s2.w += __shfl_xor_sync(~0u, s2.w, off);
    }
    if (cs == 0) {
        float m0 = s.x*(1.f/CDIM), m1 = s.y*(1.f/CDIM), m2 = s.z*(1.f/CDIM), m3 = s.w*(1.f/CDIM);
        float r0 = rsqrtf(s2.x*(1.f/CDIM) - m0*m0 + EPS);
        float r1 = rsqrtf(s2.y*(1.f/CDIM) - m1*m1 + EPS);
        float r2 = rsqrtf(s2.z*(1.f/CDIM) - m2*m2 + EPS);
        float r3 = rsqrtf(s2.w*(1.f/CDIM) - m3*m3 + EPS);
        float4* dst = (float4*)&st[(size_t)b*HW + pg*4];
        dst[0] = make_float4(m0, r0, m1, r1);
        dst[1] = make_float4(m2, r2, m3, r3);
    }
}

// ---------------- HMMA split GEMM (R13 structure) + fused inv/probe epilogue ----------------
// mode 0: plain; mode 1: q-proj (qinv + probe partials); mode 2: k-proj (kinv)
#define A_TERM 18432                      // 128*RSB
#define B_TERM 9216                       // 64*RSB
#define GEMM_SMEM (2*A_TERM + 2*B_TERM)   // 55296
__global__ void __launch_bounds__(256, 2)
hmma_gemm_k(const __nv_bfloat16* __restrict__ Wh, const __nv_bfloat16* __restrict__ Wl,
            const float* __restrict__ X,
            const float2* __restrict__ stat, const float* __restrict__ gvec,
            const float* __restrict__ bvec, float* __restrict__ C,
            int M, int N, int K, long strideX, long strideC,
            int mode, float* __restrict__ auxinv, float* __restrict__ ppart) {
    extern __shared__ char smem[];
    char* As0 = smem;
    char* As1 = smem + A_TERM;
    char* Bs0 = smem + 2*A_TERM;
    char* Bs1 = smem + 2*A_TERM + B_TERM;
    uint32_t aBase = smem_u32(As0);
    uint32_t bBase = smem_u32(Bs0);

    int tid = threadIdx.x, lane = tid & 31, wid = tid >> 5;
    int wm = wid & 3, wn = wid >> 2;
    int n0 = blockIdx.x * 64, m0 = blockIdx.y * 128;
    const float* Xp = X + (size_t)blockIdx.z * strideX;
    float* Cp = C + (size_t)blockIdx.z * strideC;

    uint32_t aLane = (uint32_t)((wm*32 + ((lane>>3)&1)*8 + (lane&7))*RSB + (lane>>4)*16);
    uint32_t bLane = (uint32_t)((((lane>>3)&1)*8 + (lane&7))*RSB + (wn*32 + (lane>>4)*8)*2);

    int ngf = tid & 7;
    float2 st8[8];
    if (stat) {
        const float2* stp = stat + (size_t)blockIdx.z * N + n0 + ngf*8;
        #pragma unroll
        for (int i = 0; i < 8; i++) st8[i] = stp[i];
    }

    float acc[2][4][4];
    #pragma unroll
    for (int i = 0; i < 2; i++)
        #pragma unroll
        for (int j = 0; j < 4; j++)
            #pragma unroll
            for (int l = 0; l < 4; l++) acc[i][j][l] = 0.f;

    int nch = K >> 6;
    for (int ch = 0; ch < nch; ch++) {
        int k0 = ch << 6;
        // stage A: pre-split bf16, pure uint4 copies
        #pragma unroll
        for (int p = 0; p < 4; p++) {
            int idx = tid + p*256;
            int m = idx >> 3, kg = idx & 7;
            size_t go = (size_t)(m0+m)*K + k0 + kg*8;
            *(uint4*)(As0 + m*RSB + kg*16) = *(const uint4*)&Wh[go];
            *(uint4*)(As1 + m*RSB + kg*16) = *(const uint4*)&Wl[go];
        }
        // stage B: raw fp32 X, optional norm, split, natural [k][n]
        #pragma unroll
        for (int p = 0; p < 2; p++) {
            int idx = tid + p*256;
            int k = idx >> 3;
            const float* src = &Xp[(size_t)(k0+k)*N + n0 + ngf*8];
            float4 x0 = *(const float4*)src;
            float4 x1 = *(const float4*)(src + 4);
            if (stat) {
                float gg = gvec[k0+k], bb = bvec[k0+k];
                x0.x = (x0.x - st8[0].x)*st8[0].y*gg + bb;
                x0.y = (x0.y - st8[1].x)*st8[1].y*gg + bb;
                x0.z = (x0.z - st8[2].x)*st8[2].y*gg + bb;
                x0.w = (x0.w - st8[3].x)*st8[3].y*gg + bb;
                x1.x = (x1.x - st8[4].x)*st8[4].y*gg + bb;
                x1.y = (x1.y - st8[5].x)*st8[5].y*gg + bb;
                x1.z = (x1.z - st8[6].x)*st8[6].y*gg + bb;
                x1.w = (x1.w - st8[7].x)*st8[7].y*gg + bb;
            }
            uint32_t h[4], l[4];
            split2(x0.x, x0.y, h[0], l[0]); split2(x0.z, x0.w, h[1], l[1]);
            split2(x1.x, x1.y, h[2], l[2]); split2(x1.z, x1.w, h[3], l[3]);
            *(uint4*)(Bs0 + k*RSB + ngf*16) = make_uint4(h[0], h[1], h[2], h[3]);
            *(uint4*)(Bs1 + k*RSB + ngf*16) = make_uint4(l[0], l[1], l[2], l[3]);
        }
        __syncthreads();

        #pragma unroll
        for (int kk = 0; kk < 4; kk++) {
            uint32_t af[2][2][4], bfr[2][4][2];
            #pragma unroll
            for (int t = 0; t < 2; t++) {
                #pragma unroll
                for (int tm = 0; tm < 2; tm++)
                    ldsm_x4(af[t][tm], aBase + t*A_TERM + tm*16*RSB + kk*32 + aLane);
                #pragma unroll
                for (int pr = 0; pr < 2; pr++) {
                    uint32_t r[4];
                    ldsm_x4_t(r, bBase + t*B_TERM + kk*16*RSB + pr*32 + bLane);
                    bfr[t][pr*2][0]   = r[0]; bfr[t][pr*2][1]   = r[1];
                    bfr[t][pr*2+1][0] = r[2]; bfr[t][pr*2+1][1] = r[3];
                }
            }
            #pragma unroll
            for (int tm = 0; tm < 2; tm++)
                #pragma unroll
                for (int tn = 0; tn < 4; tn++) {
                    mma_bf16(acc[tm][tn], af[0][tm], bfr[0][tn]);
                    mma_bf16(acc[tm][tn], af[0][tm], bfr[1][tn]);
                    mma_bf16(acc[tm][tn], af[1][tm], bfr[0][tn]);
                }
        }
        __syncthreads();
    }

    // store C
    #pragma unroll
    for (int tm = 0; tm < 2; tm++)
        #pragma unroll
        for (int tn = 0; tn < 4; tn++) {
            int r = m0 + wm*32 + tm*16 + (lane >> 2);
            int c = n0 + wn*32 + tn*8 + (lane & 3)*2;
            *(float2*)&Cp[(size_t)r*N + c]     = make_float2(acc[tm][tn][0], acc[tm][tn][1]);
            *(float2*)&Cp[(size_t)(r+8)*N + c] = make_float2(acc[tm][tn][2], acc[tm][tn][3]);
        }

    // ---- fused epilogue: per-pixel inv L2 norm over each head's 64 rows (+probe) ----
    if (mode) {
        float* ssm  = (float*)smem;          // [4 wm][64 c]
        float* invm = ssm + 256;             // [2 head][64 c]
        float* pmm  = invm + 128;            // [128 row][2 wn]
        int lr = lane >> 2, lc = lane & 3;

        #pragma unroll
        for (int tn = 0; tn < 4; tn++) {
            float s0 = 0.f, s1 = 0.f;
            #pragma unroll
            for (int tm = 0; tm < 2; tm++) {
                s0 += acc[tm][tn][0]*acc[tm][tn][0] + acc[tm][tn][2]*acc[tm][tn][2];
                s1 += acc[tm][tn][1]*acc[tm][tn][1] + acc[tm][tn][3]*acc[tm][tn][3];
            }
            #pragma unroll
            for (int off = 4; off <= 16; off <<= 1) {
                s0 += __shfl_xor_sync(~0u, s0, off);
                s1 += __shfl_xor_sync(~0u, s1, off);
            }
            if (lr == 0) {
                int c = wn*32 + tn*8 + lc*2;
                ssm[wm*64 + c]     = s0;
                ssm[wm*64 + c + 1] = s1;
            }
        }
        __syncthreads();
        if (tid < 128) {
            int head = tid >> 6, c = tid & 63;
            float ss = ssm[(head*2)*64 + c] + ssm[(head*2+1)*64 + c];
            float inv = 1.f / fmaxf(sqrtf(ss), 1e-12f);
            invm[head*64 + c] = inv;
            int bh = blockIdx.z*NHEADS + (m0 >> 6) + head;
            auxinv[(size_t)bh*N + n0 + c] = inv;
        }
        __syncthreads();

        if (mode == 1) {
            int headw = wm >> 1;
            float pr[4] = {0.f, 0.f, 0.f, 0.f};
            #pragma unroll
            for (int tn = 0; tn < 4; tn++) {
                int c = wn*32 + tn*8 + lc*2;
                float i0 = invm[headw*64 + c], i1 = invm[headw*64 + c + 1];
                #pragma unroll
                for (int tm = 0; tm < 2; tm++) {
                    pr[tm*2]     += acc[tm][tn][0]*i0 + acc[tm][tn][1]*i1;
                    pr[tm*2 + 1] += acc[tm][tn][2]*i0 + acc[tm][tn][3]*i1;
                }
            }
            #pragma unroll
            for (int off = 1; off <= 2; off <<= 1)
                #pragma unroll
                for (int r = 0; r < 4; r++) pr[r] += __shfl_xor_sync(~0u, pr[r], off);
            if (lc == 0) {
                #pragma unroll
                for (int tm = 0; tm < 2; tm++) {
                    pmm[(wm*32 + tm*16 + lr)*2 + wn]     = pr[tm*2];
                    pmm[(wm*32 + tm*16 + lr + 8)*2 + wn] = pr[tm*2 + 1];
                }
            }
            __syncthreads();
            if (tid < 128) {
                int row = tid, head = row >> 6, d = row & 63;
                float p = pmm[row*2] + pmm[row*2 + 1];
                int bh = blockIdx.z*NHEADS + (m0 >> 6) + head;
                ppart[((size_t)bh*gridDim.x + blockIdx.x)*DHEAD + d] = p;
            }
        }
    }
}

__global__ void probe_reduce_k(const float* __restrict__ part, float* __restrict__ probe) {
    int bh = blockIdx.x, d = threadIdx.x;
    float s = 0.f;
    for (int i = 0; i < NPB; i++) s += part[((size_t)bh*NPB + i)*DHEAD + d];
    probe[bh*DHEAD + d] = s;
}

// ---------------- row/col |k| sums ----------------
__global__ void rowcol_k(const float* __restrict__ k, const float* __restrict__ kinv,
                         float* __restrict__ rowsum, float* __restrict__ colsum) {
    int d = blockIdx.x, bh = blockIdx.y, t = threadIdx.x; // 64 threads
    __shared__ float s[64*65];
    const float* base = k + ((size_t)bh*DHEAD + d)*CPIX;
    const float* inv  = kinv + (size_t)bh*CPIX;
    #pragma unroll 8
    for (int h = 0; h < 64; h++) {
        int px = h*64 + t;
        s[h*65 + t] = fabsf(base[px]) * inv[px];
    }
    __syncthreads();
    float rs = 0.f, cs = 0.f;
    #pragma unroll 8
    for (int w = 0; w < 64; w++) rs += s[t*65 + w];
    #pragma unroll 8
    for (int h = 0; h < 64; h++) cs += s[h*65 + t];
    rowsum[((size_t)bh*DHEAD + d)*HC + t] = rs;
    colsum[((size_t)bh*DHEAD + d)*WC + t] = cs;
}

// ---------------- scores + exact top-8 (first index wins ties) ----------------
__global__ void topk_k(const float* __restrict__ probe, const float* __restrict__ rowsum,
                       const float* __restrict__ colsum, int* __restrict__ topidx) {
    int bh = blockIdx.x, t = threadIdx.x; // 64 threads
    __shared__ float sr[64], sc[64];
    __shared__ int th[8], tw[8];
    float r = 0.f, c = 0.f;
    for (int d = 0; d < DHEAD; d++) {
        float p = probe[bh*DHEAD + d];
        r += p * rowsum[((size_t)bh*DHEAD + d)*HC + t];
        c += p * colsum[((size_t)bh*DHEAD + d)*WC + t];
    }
    sr[t] = r; sc[t] = c;
    __syncthreads();
    if (t == 0) {
        bool used[64];
        for (int i = 0; i < 64; i++) used[i] = false;
        for (int i = 0; i < 8; i++) {
            float best = -1e38f; int bi = 0;
            for (int h = 0; h < 64; h++)
                if (!used[h] && sr[h] > best) { best = sr[h]; bi = h; }
            used[bi] = true; th[i] = bi;
        }
        for (int i = 0; i < 64; i++) used[i] = false;
        for (int i = 0; i < 8; i++) {
            float best = -1e38f; int bi = 0;
            for (int w = 0; w < 64; w++)
                if (!used[w] && sc[w] > best) { best = sc[w]; bi = w; }
            used[bi] = true; tw[i] = bi;
        }
        for (int i = 0; i < 8; i++)
            for (int j = 0; j < 8; j++)
                topidx[bh*NKV + i*8 + j] = th[i]*WC + tw[j];
    }
}

// ---------------- pack: K split [j][d]; V at pruned px split [d][j] ----------------
__global__ void pack_k(const float* __restrict__ k, const float* __restrict__ kinv,
                       const float* __restrict__ ctx_raw, const float2* __restrict__ cstat,
                       const float* __restrict__ cg, const float* __restrict__ cb_,
                       const float* __restrict__ wkv, const int* __restrict__ topidx,
                       __nv_bfloat16* __restrict__ kh, __nv_bfloat16* __restrict__ kl,
                       __nv_bfloat16* __restrict__ vh, __nv_bfloat16* __restrict__ vl) {
    extern __shared__ float ctx_s[];   // [c][j]
    __shared__ int pos[NKV];
    __shared__ float2 stj[NKV];
    int bh = blockIdx.x, b = bh >> 3, h = bh & 7;
    int tid = threadIdx.x;
    if (tid < NKV) {
        int p = topidx[bh*NKV + tid];
        pos[tid] = p;
        stj[tid] = cstat[(size_t)b*CPIX + p];
    }
    __syncthreads();

    int j = tid & 63, c0 = tid >> 6;
    float2 st = stj[j];
    for (int cc = 0; cc < 64; cc++) {
        int c = cc*4 + c0;
        float raw = ctx_raw[((size_t)b*CDIM + c)*CPIX + pos[j]];
        ctx_s[c*64 + j] = (raw - st.x)*st.y*cg[c] + cb_[c];
    }

    #pragma unroll
    for (int i = 0; i < 16; i++) {
        int idx = tid + i*256;
        int jj = idx >> 6, d = idx & 63;
        int p = pos[jj];
        float kv = k[((size_t)bh*DHEAD + d)*CPIX + p] * kinv[(size_t)bh*CPIX + p];
        __nv_bfloat16 hh, ll;
        split1(kv, hh, ll);
        kh[(size_t)bh*NKV*DHEAD + idx] = hh;
        kl[(size_t)bh*NKV*DHEAD + idx] = ll;
    }
    __syncthreads();

    for (int dd = 0; dd < 16; dd++) {
        int d = dd*4 + c0;
        const float* wr = wkv + ((size_t)(INNER + h*DHEAD + d))*CDIM;
        float acc = 0.f;
        #pragma unroll 8
        for (int c = 0; c < CDIM; c++) acc += wr[c] * ctx_s[c*64 + j];
        __nv_bfloat16 hh, ll;
        split1(acc, hh, ll);
        vh[(size_t)bh*NKV*DHEAD + d*64 + j] = hh;
        vl[(size_t)bh*NKV*DHEAD + d*64 + j] = ll;
    }
}

// ---------------- fused HMMA attention: in-register softmax, no P array ----------------
#define AQ_TERM 18432                     // 128*RSB
#define AK_TERM 9216                      // 64*RSB
#define ATTN_SMEM (2*AQ_TERM + 2*AK_TERM)   // 55296
__global__ void __launch_bounds__(256)
attn_k(const float* __restrict__ qb_all, const float* __restrict__ qinv_all,
       const __nv_bfloat16* __restrict__ kh_all, const __nv_bfloat16* __restrict__ kl_all,
       const __nv_bfloat16* __restrict__ vh_all, const __nv_bfloat16* __restrict__ vl_all,
       float* __restrict__ attno) {
    extern __shared__ char smem[];
    char* Qh = smem;                        // [px][RS]  (later Ph/Pl, then Os)
    char* Ql = smem + AQ_TERM;
    char* Kh = smem + 2*AQ_TERM;            // [j][RS] (later V [d][RS])
    char* Kl = smem + 2*AQ_TERM + AK_TERM;
    __shared__ float qiv[128];
    __shared__ float red[128][2];
    uint32_t qBase = smem_u32(Qh);
    uint32_t kBase = smem_u32(Kh);

    int bh = blockIdx.y;
    int px0 = blockIdx.x * 128;
    int tid = threadIdx.x, lane = tid & 31, wid = tid >> 5;
    int wm = wid & 3, wn = wid >> 2;
    int lr = lane >> 2, lc = lane & 3;

    const float* qb = qb_all + (size_t)bh*DHEAD*NPIX + px0;
    const float* qi = qinv_all + (size_t)bh*NPIX + px0;
    const uint32_t* khp = (const uint32_t*)(kh_all + (size_t)bh*NKV*DHEAD);
    const uint32_t* klp = (const uint32_t*)(kl_all + (size_t)bh*NKV*DHEAD);
    const uint32_t* vhp = (const uint32_t*)(vh_all + (size_t)bh*NKV*DHEAD);
    const uint32_t* vlp = (const uint32_t*)(vl_all + (size_t)bh*NKV*DHEAD);

    uint32_t aLane = (uint32_t)((wm*32 + ((lane>>3)&1)*8 + (lane&7))*RSB + (lane>>4)*16);
    uint32_t bLane = (uint32_t)(((lane>>4)*8 + (lane&7))*RSB + ((lane>>3)&1)*16 + wn*32*RSB);

    if (tid < 128) qiv[tid] = qi[tid];
    for (int i = tid; i < 2048; i += 256) {
        int j = i >> 5, dp = i & 31;
        ((uint32_t*)(Kh + j*RSB))[dp] = khp[i];
        ((uint32_t*)(Kl + j*RSB))[dp] = klp[i];
    }
    __syncthreads();
    #pragma unroll
    for (int it = 0; it < 16; it++) {
        int idx = tid + it*256;
        int p  = (idx & 7) | (((idx >> 5) & 15) << 3);
        int dp = ((idx >> 3) & 3) | ((idx >> 9) << 2);
        float iv = qiv[p];
        float v0 = qb[(size_t)(2*dp)*NPIX + p] * iv;
        float v1 = qb[(size_t)(2*dp+1)*NPIX + p] * iv;
        uint32_t hi, lo;
        split2(v0, v1, hi, lo);
        ((uint32_t*)(Qh + p*RSB))[dp] = hi;
        ((uint32_t*)(Ql + p*RSB))[dp] = lo;
    }
    __syncthreads();

    // QK^T -> acc (registers)
    float acc[2][4][4];
    #pragma unroll
    for (int i = 0; i < 2; i++)
        #pragma unroll
        for (int j = 0; j < 4; j++)
            #pragma unroll
            for (int l = 0; l < 4; l++) acc[i][j][l] = 0.f;
    #pragma unroll
    for (int kk = 0; kk < 4; kk++) {
        uint32_t af[2][2][4], bfr[2][4][2];
        #pragma unroll
        for (int t = 0; t < 2; t++) {
            #pragma unroll
            for (int tm = 0; tm < 2; tm++)
                ldsm_x4(af[t][tm], qBase + t*AQ_TERM + tm*16*RSB + kk*32 + aLane);
            #pragma unroll
            for (int pr = 0; pr < 2; pr++) {
                uint32_t r[4];
                ldsm_x4(r, kBase + t*AK_TERM + pr*16*RSB + kk*32 + bLane);
                bfr[t][pr*2][0]   = r[0]; bfr[t][pr*2][1]   = r[1];
                bfr[t][pr*2+1][0] = r[2]; bfr[t][pr*2+1][1] = r[3];
            }
        }
        #pragma unroll
        for (int tm = 0; tm < 2; tm++)
            #pragma unroll
            for (int tn = 0; tn < 4; tn++) {
                mma_bf16(acc[tm][tn], af[0][tm], bfr[0][tn]);
                mma_bf16(acc[tm][tn], af[0][tm], bfr[1][tn]);
                mma_bf16(acc[tm][tn], af[1][tm], bfr[0][tn]);
            }
    }
    __syncthreads();   // all K/Q smem reads done

    // stage V into K region ([d][RS])
    for (int i = tid; i < 2048; i += 256) {
        int d = i >> 5, jp = i & 31;
        ((uint32_t*)(Kh + d*RSB))[jp] = vhp[i];
        ((uint32_t*)(Kl + d*RSB))[jp] = vlp[i];
    }

    // ---- in-register softmax over j ----
    float mrow[2][2];
    #pragma unroll
    for (int tm = 0; tm < 2; tm++) {
        float m0 = -1e30f, m1 = -1e30f;
        #pragma unroll
        for (int tn = 0; tn < 4; tn++) {
            m0 = fmaxf(m0, fmaxf(acc[tm][tn][0], acc[tm][tn][1]));
            m1 = fmaxf(m1, fmaxf(acc[tm][tn][2], acc[tm][tn][3]));
        }
        #pragma unroll
        for (int off = 1; off <= 2; off <<= 1) {
            m0 = fmaxf(m0, __shfl_xor_sync(~0u, m0, off));
            m1 = fmaxf(m1, __shfl_xor_sync(~0u, m1, off));
        }
        mrow[tm][0] = m0; mrow[tm][1] = m1;
    }
    if (lc == 0) {
        #pragma unroll
        for (int tm = 0; tm < 2; tm++) {
            red[wm*32 + tm*16 + lr][wn]     = mrow[tm][0];
            red[wm*32 + tm*16 + lr + 8][wn] = mrow[tm][1];
        }
    }
    __syncthreads();
    float fm[2][2];
    #pragma unroll
    for (int tm = 0; tm < 2; tm++) {
        fm[tm][0] = fmaxf(red[wm*32 + tm*16 + lr][0],     red[wm*32 + tm*16 + lr][1]);
        fm[tm][1] = fmaxf(red[wm*32 + tm*16 + lr + 8][0], red[wm*32 + tm*16 + lr + 8][1]);
    }
    __syncthreads();
    float srow[2][2] = {{0.f,0.f},{0.f,0.f}};
    #pragma unroll
    for (int tm = 0; tm < 2; tm++)
        #pragma unroll
        for (int tn = 0; tn < 4; tn++) {
            acc[tm][tn][0] = expf(acc[tm][tn][0] - fm[tm][0]);
            acc[tm][tn][1] = expf(acc[tm][tn][1] - fm[tm][0]);
            acc[tm][tn][2] = expf(acc[tm][tn][2] - fm[tm][1]);
            acc[tm][tn][3] = expf(acc[tm][tn][3] - fm[tm][1]);
            srow[tm][0] += acc[tm][tn][0] + acc[tm][tn][1];
            srow[tm][1] += acc[tm][tn][2] + acc[tm][tn][3];
        }
    #pragma unroll
    for (int tm = 0; tm < 2; tm++)
        #pragma unroll
        for (int off = 1; off <= 2; off <<= 1) {
            srow[tm][0] += __shfl_xor_sync(~0u, srow[tm][0], off);
            srow[tm][1] += __shfl_xor_sync(~0u, srow[tm][1], off);
        }
    if (lc == 0) {
        #pragma unroll
        for (int tm = 0; tm < 2; tm++) {
            red[wm*32 + tm*16 + lr][wn]     = srow[tm][0];
            red[wm*32 + tm*16 + lr + 8][wn] = srow[tm][1];
        }
    }
    __syncthreads();
    float fs[2][2];
    #pragma unroll
    for (int tm = 0; tm < 2; tm++) {
        fs[tm][0] = 1.f / (red[wm*32 + tm*16 + lr][0]     + red[wm*32 + tm*16 + lr][1]);
        fs[tm][1] = 1.f / (red[wm*32 + tm*16 + lr + 8][0] + red[wm*32 + tm*16 + lr + 8][1]);
    }

    // scale + split directly into Qh/Ql as P tiles [r][j]
    #pragma unroll
    for (int tm = 0; tm < 2; tm++)
        #pragma unroll
        for (int tn = 0; tn < 4; tn++) {
            int r1 = wm*32 + tm*16 + lr;
            int cw = wn*16 + tn*4 + lc;   // uint32 index = col/2
            float p0 = acc[tm][tn][0] * fs[tm][0];
            float p1 = acc[tm][tn][1] * fs[tm][0];
            float p2 = acc[tm][tn][2] * fs[tm][1];
            float p3 = acc[tm][tn][3] * fs[tm][1];
            uint32_t hi, lo;
            split2(p0, p1, hi, lo);
            ((uint32_t*)(Qh + r1*RSB))[cw] = hi;
            ((uint32_t*)(Ql + r1*RSB))[cw] = lo;
            split2(p2, p3, hi, lo);
            ((uint32_t*)(Qh + (r1+8)*RSB))[cw] = hi;
            ((uint32_t*)(Ql + (r1+8)*RSB))[cw] = lo;
        }
    __syncthreads();

    // P @ V -> out[px][d]
    {
        float acc2[2][4][4];
        #pragma unroll
        for (int i = 0; i < 2; i++)
            #pragma unroll
            for (int j = 0; j < 4; j++)
                #pragma unroll
                for (int l = 0; l < 4; l++) acc2[i][j][l] = 0.f;
        #pragma unroll
        for (int kk = 0; kk < 4; kk++) {
            uint32_t af[2][2][4], bfr[2][4][2];
            #pragma unroll
            for (int t = 0; t < 2; t++) {
                #pragma unroll
                for (int tm = 0; tm < 2; tm++)
                    ldsm_x4(af[t][tm], qBase + t*AQ_TERM + tm*16*RSB + kk*32 + aLane);
                #pragma unroll
                for (int pr = 0; pr < 2; pr++) {
                    uint32_t r[4];
                    ldsm_x4(r, kBase + t*AK_TERM + pr*16*RSB + kk*32 + bLane);
                    bfr[t][pr*2][0]   = r[0]; bfr[t][pr*2][1]   = r[1];
                    bfr[t][pr*2+1][0] = r[2]; bfr[t][pr*2+1][1] = r[3];
                }
            }
            #pragma unroll
            for (int tm = 0; tm < 2; tm++)
                #pragma unroll
                for (int tn = 0; tn < 4; tn++) {
                    mma_bf16(acc2[tm][tn], af[0][tm], bfr[0][tn]);
                    mma_bf16(acc2[tm][tn], af[0][tm], bfr[1][tn]);
                    mma_bf16(acc2[tm][tn], af[1][tm], bfr[0][tn]);
                }
        }
        __syncthreads();   // P/V reads done; reuse Qh/Ql region as Os [64][132] fp32
        float* Os = (float*)Qh;
        #pragma unroll
        for (int tm = 0; tm < 2; tm++)
            #pragma unroll
            for (int tn = 0; tn < 4; tn++) {
                int r = wm*32 + tm*16 + lr;
                int c = wn*32 + tn*8 + lc*2;
                Os[c*132 + r]       = acc2[tm][tn][0];
                Os[(c+1)*132 + r]   = acc2[tm][tn][1];
                Os[c*132 + r + 8]   = acc2[tm][tn][2];
                Os[(c+1)*132 + r+8] = acc2[tm][tn][3];
            }
        __syncthreads();
        float* ob = attno + (size_t)bh*DHEAD*NPIX + px0;
        for (int i = tid; i < 8192; i += 256) {
            int d = i >> 7, p = i & 127;
            ob[(size_t)d*NPIX + p] = Os[d*132 + p];
        }
    }
}

// ---------------- final (float4 + c-split-8, 128 px/block): channorm*gamma + residual ----------------
__global__ void final_k(const float* __restrict__ x, const float* __restrict__ g,
                        const float* __restrict__ bb, const float* __restrict__ gamma,
                        const float* __restrict__ resid, float* __restrict__ y) {
    int tid = threadIdx.x;
    int cs = tid & 7, pg = blockIdx.x*32 + (tid >> 3);
    int b  = blockIdx.y;
    const float4* xb = (const float4*)(x + (size_t)b*CDIM*NPIX) + pg;
    const float4* rb = (const float4*)(resid + (size_t)b*CDIM*NPIX) + pg;
    float4* yb = (float4*)(y + (size_t)b*CDIM*NPIX) + pg;
    int c0 = cs*32, hw4 = NPIX >> 2;
    float4 s = {0,0,0,0}, s2 = {0,0,0,0};
    #pragma unroll 16
    for (int i = 0; i < 32; i++) {
        float4 v = xb[(size_t)(c0+i)*hw4];
        s.x += v.x; s.y += v.y; s.z += v.z; s.w += v.w;
        s2.x += v.x*v.x; s2.y += v.y*v.y; s2.z += v.z*v.z; s2.w += v.w*v.w;
    }
    #pragma unroll
    for (int off = 1; off <= 4; off <<= 1) {
        s.x += __shfl_xor_sync(~0u, s.x, off);  s.y += __shfl_xor_sync(~0u, s.y, off);
        s.z += __shfl_xor_sync(~0u, s.z, off);  s.w += __shfl_xor_sync(~0u, s.w, off);
        s2.x += __shfl_xor_sync(~0u, s2.x, off); s2.y += __shfl_xor_sync(~0u, s2.y, off);
        s2.z += __shfl_xor_sync(~0u, s2.z, off); s2.w += __shfl_xor_sync(~0u, s2.w, off);
    }
    float m0 = s.x*(1.f/CDIM), m1 = s.y*(1.f/CDIM), m2 = s.z*(1.f/CDIM), m3 = s.w*(1.f/CDIM);
    float r0 = rsqrtf(s2.x*(1.f/CDIM) - m0*m0 + EPS);
    float r1 = rsqrtf(s2.y*(1.f/CDIM) - m1*m1 + EPS);
    float r2 = rsqrtf(s2.z*(1.f/CDIM) - m2*m2 + EPS);
    float r3 = rsqrtf(s2.w*(1.f/CDIM) - m3*m3 + EPS);
    float gm = gamma[0];
    #pragma unroll 8
    for (int i = 0; i < 32; i++) {
        int c = c0 + i;
        float4 v = xb[(size_t)c*hw4];
        float4 rr = rb[(size_t)c*hw4];
        float gg = g[c], bv = bb[c];
        float4 o;
        o.x = gm*((v.x - m0)*r0*gg + bv) + rr.x;
        o.y = gm*((v.y - m1)*r1*gg + bv) + rr.y;
        o.z = gm*((v.z - m2)*r2*gg + bv) + rr.z;
        o.w = gm*((v.w - m3)*r3*gg + bv) + rr.w;
        yb[(size_t)c*hw4] = o;
    }
}

// ---------------- launch ----------------
extern "C" void kernel_launch(void* const* d_in, const int* in_sizes, int n_in,
                              void* d_out, int out_size) {
    const float* query_source = (const float*)d_in[0];
    const float* context      = (const float*)d_in[1];
    const float* qs_g  = (const float*)d_in[2];
    const float* qs_b  = (const float*)d_in[3];
    const float* ctx_g = (const float*)d_in[4];
    const float* ctx_b = (const float*)d_in[5];
    const float* out_g = (const float*)d_in[6];
    const float* out_b = (const float*)d_in[7];
    const float* w_q   = (const float*)d_in[8];
    const float* w_kv  = (const float*)d_in[9];
    const float* w_out = (const float*)d_in[10];
    const float* gamma = (const float*)d_in[11];
    float* out = (float*)d_out;

    float *qb, *kb, *attno, *obuf, *qinv, *kinv, *ppart, *probe, *rowsum, *colsum;
    int* topidx;
    float2 *cstat, *qstat;
    __nv_bfloat16 *kh, *kl, *vh, *vl, *wqh, *wql, *wkh, *wkl, *woh, *wol;
    cudaGetSymbolAddress((void**)&qb,    g_q);
    cudaGetSymbolAddress((void**)&kb,    g_k);
    cudaGetSymbolAddress((void**)&attno, g_attno);
    cudaGetSymbolAddress((void**)&obuf,  g_obuf);
    cudaGetSymbolAddress((void**)&qinv,  g_qinv);
    cudaGetSymbolAddress((void**)&kinv,  g_kinv);
    cudaGetSymbolAddress((void**)&ppart, g_probe_part);
    cudaGetSymbolAddress((void**)&probe, g_probe);
    cudaGetSymbolAddress((void**)&rowsum,g_rowsum);
    cudaGetSymbolAddress((void**)&colsum,g_colsum);
    cudaGetSymbolAddress((void**)&topidx,g_topidx);
    cudaGetSymbolAddress((void**)&cstat, g_ctx_stat);
    cudaGetSymbolAddress((void**)&qstat, g_qs_stat);
    cudaGetSymbolAddress((void**)&kh,    g_kh);
    cudaGetSymbolAddress((void**)&kl,    g_kl);
    cudaGetSymbolAddress((void**)&vh,    g_vh);
    cudaGetSymbolAddress((void**)&vl,    g_vl);
    cudaGetSymbolAddress((void**)&wqh,   g_wq_h);
    cudaGetSymbolAddress((void**)&wql,   g_wq_l);
    cudaGetSymbolAddress((void**)&wkh,   g_wk_h);
    cudaGetSymbolAddress((void**)&wkl,   g_wk_l);
    cudaGetSymbolAddress((void**)&woh,   g_wo_h);
    cudaGetSymbolAddress((void**)&wol,   g_wo_l);

    cudaFuncSetAttribute(hmma_gemm_k, cudaFuncAttributeMaxDynamicSharedMemorySize, GEMM_SMEM);
    cudaFuncSetAttribute(attn_k, cudaFuncAttributeMaxDynamicSharedMemorySize, ATTN_SMEM);
    cudaFuncSetAttribute(pack_k, cudaFuncAttributeMaxDynamicSharedMemorySize, 256*64*4);

    // 0) weight splits (tiny)
    split_w_k<<<(INNER*CDIM/4 + 255)/256, 256>>>(w_q,   wqh, wql, INNER*CDIM);
    split_w_k<<<(INNER*CDIM/4 + 255)/256, 256>>>(w_kv,  wkh, wkl, INNER*CDIM);  // K half
    split_w_k<<<(CDIM*INNER/4 + 255)/256, 256>>>(w_out, woh, wol, CDIM*INNER);

    // 1) per-pixel layernorm stats (128 px/block for higher occupancy)
    stat_k<<<dim3(CPIX/128, BATCH), 256>>>(context, cstat, CPIX);
    stat_k<<<dim3(NPIX/128, BATCH), 256>>>(query_source, qstat, NPIX);

    // 2) projections with fused inv/probe epilogues
    hmma_gemm_k<<<dim3(CPIX/64, INNER/128, BATCH), 256, GEMM_SMEM>>>(
        wkh, wkl, context, cstat, ctx_g, ctx_b, kb, INNER, CPIX, CDIM,
        (long)CDIM*CPIX, (long)INNER*CPIX, 2, kinv, nullptr);
    hmma_gemm_k<<<dim3(NPIX/64, INNER/128, BATCH), 256, GEMM_SMEM>>>(
        wqh, wql, query_source, qstat, qs_g, qs_b, qb, INNER, NPIX, CDIM,
        (long)CDIM*NPIX, (long)INNER*NPIX, 1, qinv, ppart);

    // 3) probe + pruning scores
    probe_reduce_k<<<BH, DHEAD>>>(ppart, probe);
    rowcol_k<<<dim3(DHEAD, BH), 64>>>(kb, kinv, rowsum, colsum);
    topk_k<<<BH, 64>>>(probe, rowsum, colsum, topidx);

    // 4) pack pruned K (split) + compute pruned V (split, transposed)
    pack_k<<<BH, 256, 256*64*4>>>(kb, kinv, context, cstat, ctx_g, ctx_b,
                                  w_kv, topidx, kh, kl, vh, vl);

    // 5) fused HMMA attention (in-register softmax)
    attn_k<<<dim3(NPIX/128, BH), 256, ATTN_SMEM>>>(qb, qinv, kh, kl, vh, vl, attno);

    // 6) output projection
    hmma_gemm_k<<<dim3(NPIX/64, CDIM/128, BATCH), 256, GEMM_SMEM>>>(
        woh, wol, attno, nullptr, nullptr, nullptr, obuf, CDIM, NPIX, INNER,
        (long)INNER*NPIX, (long)CDIM*NPIX, 0, nullptr, nullptr);

    // 7) final norm + gamma + residual (128 px/block)
    final_k<<<dim3(NPIX/128, BATCH), 256>>>(obuf, out_g, out_b, gamma, query_source, out);
}

// round 16
// speedup vs baseline: 1.0649x; 1.0434x over previous
#include <cuda_runtime.h>
#include <cuda_bf16.h>
#include <math.h>
#include <stdint.h>

// ---------------- problem dims ----------------
#define BATCH   8
#define CDIM    256
#define INNER   512
#define NHEADS  8
#define DHEAD   64
#define HQ      96
#define WQ      96
#define NPIX    (HQ*WQ)     // 9216
#define HC      64
#define WC      64
#define CPIX    (HC*WC)     // 4096
#define BH      (BATCH*NHEADS) // 64
#define NKV     64          // 8x8 pruned
#define EPS     1e-5f
#define NPB     (NPIX/64)   // 144 probe partial blocks per bh

// ---------------- scratch (static device memory; no allocs) ----------------
__device__ float  g_q    [BATCH*INNER*NPIX];   // q projection [bh][d][px]
__device__ float  g_k    [BATCH*INNER*CPIX];   // k projection [bh][d][px]
__device__ float  g_attno[BATCH*INNER*NPIX];   // attention out [bh][d][px]
__device__ float  g_obuf [BATCH*CDIM*NPIX];
__device__ float  g_qinv [BH*NPIX];
__device__ float  g_kinv [BH*CPIX];
__device__ float  g_probe_part[BH*NPB*DHEAD];
__device__ float  g_probe[BH*DHEAD];
__device__ float  g_rowsum[BH*DHEAD*HC];
__device__ float  g_colsum[BH*DHEAD*WC];
__device__ int    g_topidx[BH*NKV];
__device__ float2 g_ctx_stat[BATCH*CPIX];
__device__ float2 g_qs_stat [BATCH*NPIX];
__device__ float2 g_opart[BATCH*2*NPIX];       // per-pixel (sum, sumsq) partials (2 channel halves)
__device__ float2 g_ostat[BATCH*NPIX];         // per-pixel (mean, rstd) for final norm
__device__ __nv_bfloat16 g_kh[BH*NKV*DHEAD], g_kl[BH*NKV*DHEAD];  // [j][d]
__device__ __nv_bfloat16 g_vh[BH*NKV*DHEAD], g_vl[BH*NKV*DHEAD];  // [d][j]
// pre-split weights (bf16 hi/lo)
__device__ __nv_bfloat16 g_wq_h [INNER*CDIM], g_wq_l [INNER*CDIM];
__device__ __nv_bfloat16 g_wk_h [INNER*CDIM], g_wk_l [INNER*CDIM];
__device__ __nv_bfloat16 g_wo_h [CDIM*INNER], g_wo_l [CDIM*INNER];

// ---------------- helpers ----------------
__device__ __forceinline__ uint32_t smem_u32(const void* p) {
    uint32_t a;
    asm("{ .reg .u64 t; cvta.to.shared.u64 t, %1; cvt.u32.u64 %0, t; }" : "=r"(a) : "l"(p));
    return a;
}
__device__ __forceinline__ unsigned short bf_bits(__nv_bfloat16 h) {
    return *reinterpret_cast<unsigned short*>(&h);
}
__device__ __forceinline__ void split1(float v, __nv_bfloat16& h, __nv_bfloat16& l) {
    h = __float2bfloat16(v);
    l = __float2bfloat16(v - __bfloat162float(h));
}
__device__ __forceinline__ void split2(float a, float b, uint32_t& hi, uint32_t& lo) {
    __nv_bfloat16 ha, la, hb, lb;
    split1(a, ha, la); split1(b, hb, lb);
    hi = (uint32_t)bf_bits(ha) | ((uint32_t)bf_bits(hb) << 16);
    lo = (uint32_t)bf_bits(la) | ((uint32_t)bf_bits(lb) << 16);
}
__device__ __forceinline__ void mma_bf16(float* c, const uint32_t* a, const uint32_t* b) {
    asm volatile(
        "mma.sync.aligned.m16n8k16.row.col.f32.bf16.bf16.f32 "
        "{%0,%1,%2,%3}, {%4,%5,%6,%7}, {%8,%9}, {%0,%1,%2,%3};\n"
        : "+f"(c[0]), "+f"(c[1]), "+f"(c[2]), "+f"(c[3])
        : "r"(a[0]), "r"(a[1]), "r"(a[2]), "r"(a[3]), "r"(b[0]), "r"(b[1]));
}
__device__ __forceinline__ void ldsm_x4(uint32_t* r, uint32_t addr) {
    asm volatile("ldmatrix.sync.aligned.m8n8.x4.shared.b16 {%0,%1,%2,%3}, [%4];"
        : "=r"(r[0]), "=r"(r[1]), "=r"(r[2]), "=r"(r[3]) : "r"(addr));
}
__device__ __forceinline__ void ldsm_x4_t(uint32_t* r, uint32_t addr) {
    asm volatile("ldmatrix.sync.aligned.m8n8.x4.trans.shared.b16 {%0,%1,%2,%3}, [%4];"
        : "=r"(r[0]), "=r"(r[1]), "=r"(r[2]), "=r"(r[3]) : "r"(addr));
}

// row stride for bf16 tiles: 72 elems = 144 B (16B-aligned, conflict-free LDSM)
#define RS   72
#define RSB  144

// ---------------- weight hi/lo split (runs once, tiny) ----------------
__global__ void split_w_k(const float* __restrict__ src, __nv_bfloat16* __restrict__ dh,
                          __nv_bfloat16* __restrict__ dl, int n) {
    int i = blockIdx.x*256 + threadIdx.x;
    if (i*4 < n) {
        float4 v = *(const float4*)&src[i*4];
        uint32_t h01, l01, h23, l23;
        split2(v.x, v.y, h01, l01);
        split2(v.z, v.w, h23, l23);
        *(uint2*)&dh[i*4] = make_uint2(h01, h23);
        *(uint2*)&dl[i*4] = make_uint2(l01, l23);
    }
}

// ---------------- per-pixel layernorm stats (float4 + c-split-8, 128 px/block) ----------------
__global__ void stat_k(const float* __restrict__ x, float2* __restrict__ st, int HW) {
    int tid = threadIdx.x;
    int cs = tid & 7, pg = blockIdx.x*32 + (tid >> 3);
    int b  = blockIdx.y;
    const float4* xb = (const float4*)(x + (size_t)b*CDIM*HW) + pg;
    int c0 = cs*32, hw4 = HW >> 2;
    float4 s = {0,0,0,0}, s2 = {0,0,0,0};
    #pragma unroll 16
    for (int i = 0; i < 32; i++) {
        float4 v = xb[(size_t)(c0+i)*hw4];
        s.x += v.x; s.y += v.y; s.z += v.z; s.w += v.w;
        s2.x += v.x*v.x; s2.y += v.y*v.y; s2.z += v.z*v.z; s2.w += v.w*v.w;
    }
    #pragma unroll
    for (int off = 1; off <= 4; off <<= 1) {
        s.x += __shfl_xor_sync(~0u, s.x, off);  s.y += __shfl_xor_sync(~0u, s.y, off);
        s.z += __shfl_xor_sync(~0u, s.z, off);  s.w += __shfl_xor_sync(~0u, s.w, off);
        s2.x += __shfl_xor_sync(~0u, s2.x, off); s2.y += __shfl_xor_sync(~0u, s2.y, off);
        s2.z += __shfl_xor_sync(~0u, s2.z, off); s2.w += __shfl_xor_sync(~0u, s2.w, off);
    }
    if (cs == 0) {
        float m0 = s.x*(1.f/CDIM), m1 = s.y*(1.f/CDIM), m2 = s.z*(1.f/CDIM), m3 = s.w*(1.f/CDIM);
        float r0 = rsqrtf(s2.x*(1.f/CDIM) - m0*m0 + EPS);
        float r1 = rsqrtf(s2.y*(1.f/CDIM) - m1*m1 + EPS);
        float r2 = rsqrtf(s2.z*(1.f/CDIM) - m2*m2 + EPS);
        float r3 = rsqrtf(s2.w*(1.f/CDIM) - m3*m3 + EPS);
        float4* dst = (float4*)&st[(size_t)b*HW + pg*4];
        dst[0] = make_float4(m0, r0, m1, r1);
        dst[1] = make_float4(m2, r2, m3, r3);
    }
}

// ---------------- HMMA split GEMM (R13 structure) + fused epilogues ----------------
// mode 0: plain; 1: q-proj (qinv+probe); 2: k-proj (kinv); 3: out-proj (per-px sum/sumsq partials)
#define A_TERM 18432                      // 128*RSB
#define B_TERM 9216                       // 64*RSB
#define GEMM_SMEM (2*A_TERM + 2*B_TERM)   // 55296
__global__ void __launch_bounds__(256, 2)
hmma_gemm_k(const __nv_bfloat16* __restrict__ Wh, const __nv_bfloat16* __restrict__ Wl,
            const float* __restrict__ X,
            const float2* __restrict__ stat, const float* __restrict__ gvec,
            const float* __restrict__ bvec, float* __restrict__ C,
            int M, int N, int K, long strideX, long strideC,
            int mode, float* __restrict__ auxinv, float* __restrict__ ppart) {
    extern __shared__ char smem[];
    char* As0 = smem;
    char* As1 = smem + A_TERM;
    char* Bs0 = smem + 2*A_TERM;
    char* Bs1 = smem + 2*A_TERM + B_TERM;
    uint32_t aBase = smem_u32(As0);
    uint32_t bBase = smem_u32(Bs0);

    int tid = threadIdx.x, lane = tid & 31, wid = tid >> 5;
    int wm = wid & 3, wn = wid >> 2;
    int n0 = blockIdx.x * 64, m0 = blockIdx.y * 128;
    const float* Xp = X + (size_t)blockIdx.z * strideX;
    float* Cp = C + (size_t)blockIdx.z * strideC;

    uint32_t aLane = (uint32_t)((wm*32 + ((lane>>3)&1)*8 + (lane&7))*RSB + (lane>>4)*16);
    uint32_t bLane = (uint32_t)((((lane>>3)&1)*8 + (lane&7))*RSB + (wn*32 + (lane>>4)*8)*2);

    int ngf = tid & 7;
    float2 st8[8];
    if (stat) {
        const float2* stp = stat + (size_t)blockIdx.z * N + n0 + ngf*8;
        #pragma unroll
        for (int i = 0; i < 8; i++) st8[i] = stp[i];
    }

    float acc[2][4][4];
    #pragma unroll
    for (int i = 0; i < 2; i++)
        #pragma unroll
        for (int j = 0; j < 4; j++)
            #pragma unroll
            for (int l = 0; l < 4; l++) acc[i][j][l] = 0.f;

    int nch = K >> 6;
    for (int ch = 0; ch < nch; ch++) {
        int k0 = ch << 6;
        // stage A: pre-split bf16, pure uint4 copies
        #pragma unroll
        for (int p = 0; p < 4; p++) {
            int idx = tid + p*256;
            int m = idx >> 3, kg = idx & 7;
            size_t go = (size_t)(m0+m)*K + k0 + kg*8;
            *(uint4*)(As0 + m*RSB + kg*16) = *(const uint4*)&Wh[go];
            *(uint4*)(As1 + m*RSB + kg*16) = *(const uint4*)&Wl[go];
        }
        // stage B: raw fp32 X, optional norm, split, natural [k][n]
        #pragma unroll
        for (int p = 0; p < 2; p++) {
            int idx = tid + p*256;
            int k = idx >> 3;
            const float* src = &Xp[(size_t)(k0+k)*N + n0 + ngf*8];
            float4 x0 = *(const float4*)src;
            float4 x1 = *(const float4*)(src + 4);
            if (stat) {
                float gg = gvec[k0+k], bb = bvec[k0+k];
                x0.x = (x0.x - st8[0].x)*st8[0].y*gg + bb;
                x0.y = (x0.y - st8[1].x)*st8[1].y*gg + bb;
                x0.z = (x0.z - st8[2].x)*st8[2].y*gg + bb;
                x0.w = (x0.w - st8[3].x)*st8[3].y*gg + bb;
                x1.x = (x1.x - st8[4].x)*st8[4].y*gg + bb;
                x1.y = (x1.y - st8[5].x)*st8[5].y*gg + bb;
                x1.z = (x1.z - st8[6].x)*st8[6].y*gg + bb;
                x1.w = (x1.w - st8[7].x)*st8[7].y*gg + bb;
            }
            uint32_t h[4], l[4];
            split2(x0.x, x0.y, h[0], l[0]); split2(x0.z, x0.w, h[1], l[1]);
            split2(x1.x, x1.y, h[2], l[2]); split2(x1.z, x1.w, h[3], l[3]);
            *(uint4*)(Bs0 + k*RSB + ngf*16) = make_uint4(h[0], h[1], h[2], h[3]);
            *(uint4*)(Bs1 + k*RSB + ngf*16) = make_uint4(l[0], l[1], l[2], l[3]);
        }
        __syncthreads();

        #pragma unroll
        for (int kk = 0; kk < 4; kk++) {
            uint32_t af[2][2][4], bfr[2][4][2];
            #pragma unroll
            for (int t = 0; t < 2; t++) {
                #pragma unroll
                for (int tm = 0; tm < 2; tm++)
                    ldsm_x4(af[t][tm], aBase + t*A_TERM + tm*16*RSB + kk*32 + aLane);
                #pragma unroll
                for (int pr = 0; pr < 2; pr++) {
                    uint32_t r[4];
                    ldsm_x4_t(r, bBase + t*B_TERM + kk*16*RSB + pr*32 + bLane);
                    bfr[t][pr*2][0]   = r[0]; bfr[t][pr*2][1]   = r[1];
                    bfr[t][pr*2+1][0] = r[2]; bfr[t][pr*2+1][1] = r[3];
                }
            }
            #pragma unroll
            for (int tm = 0; tm < 2; tm++)
                #pragma unroll
                for (int tn = 0; tn < 4; tn++) {
                    mma_bf16(acc[tm][tn], af[0][tm], bfr[0][tn]);
                    mma_bf16(acc[tm][tn], af[0][tm], bfr[1][tn]);
                    mma_bf16(acc[tm][tn], af[1][tm], bfr[0][tn]);
                }
        }
        __syncthreads();
    }

    // store C
    #pragma unroll
    for (int tm = 0; tm < 2; tm++)
        #pragma unroll
        for (int tn = 0; tn < 4; tn++) {
            int r = m0 + wm*32 + tm*16 + (lane >> 2);
            int c = n0 + wn*32 + tn*8 + (lane & 3)*2;
            *(float2*)&Cp[(size_t)r*N + c]     = make_float2(acc[tm][tn][0], acc[tm][tn][1]);
            *(float2*)&Cp[(size_t)(r+8)*N + c] = make_float2(acc[tm][tn][2], acc[tm][tn][3]);
        }

    // ---- fused epilogues ----
    if (mode == 1 || mode == 2) {
        float* ssm  = (float*)smem;          // [4 wm][64 c]
        float* invm = ssm + 256;             // [2 head][64 c]
        float* pmm  = invm + 128;            // [128 row][2 wn]
        int lr = lane >> 2, lc = lane & 3;

        #pragma unroll
        for (int tn = 0; tn < 4; tn++) {
            float s0 = 0.f, s1 = 0.f;
            #pragma unroll
            for (int tm = 0; tm < 2; tm++) {
                s0 += acc[tm][tn][0]*acc[tm][tn][0] + acc[tm][tn][2]*acc[tm][tn][2];
                s1 += acc[tm][tn][1]*acc[tm][tn][1] + acc[tm][tn][3]*acc[tm][tn][3];
            }
            #pragma unroll
            for (int off = 4; off <= 16; off <<= 1) {
                s0 += __shfl_xor_sync(~0u, s0, off);
                s1 += __shfl_xor_sync(~0u, s1, off);
            }
            if (lr == 0) {
                int c = wn*32 + tn*8 + lc*2;
                ssm[wm*64 + c]     = s0;
                ssm[wm*64 + c + 1] = s1;
            }
        }
        __syncthreads();
        if (tid < 128) {
            int head = tid >> 6, c = tid & 63;
            float ss = ssm[(head*2)*64 + c] + ssm[(head*2+1)*64 + c];
            float inv = 1.f / fmaxf(sqrtf(ss), 1e-12f);
            invm[head*64 + c] = inv;
            int bh = blockIdx.z*NHEADS + (m0 >> 6) + head;
            auxinv[(size_t)bh*N + n0 + c] = inv;
        }
        __syncthreads();

        if (mode == 1) {
            int headw = wm >> 1;
            float pr[4] = {0.f, 0.f, 0.f, 0.f};
            #pragma unroll
            for (int tn = 0; tn < 4; tn++) {
                int c = wn*32 + tn*8 + lc*2;
                float i0 = invm[headw*64 + c], i1 = invm[headw*64 + c + 1];
                #pragma unroll
                for (int tm = 0; tm < 2; tm++) {
                    pr[tm*2]     += acc[tm][tn][0]*i0 + acc[tm][tn][1]*i1;
                    pr[tm*2 + 1] += acc[tm][tn][2]*i0 + acc[tm][tn][3]*i1;
                }
            }
            #pragma unroll
            for (int off = 1; off <= 2; off <<= 1)
                #pragma unroll
                for (int r = 0; r < 4; r++) pr[r] += __shfl_xor_sync(~0u, pr[r], off);
            if (lc == 0) {
                #pragma unroll
                for (int tm = 0; tm < 2; tm++) {
                    pmm[(wm*32 + tm*16 + lr)*2 + wn]     = pr[tm*2];
                    pmm[(wm*32 + tm*16 + lr + 8)*2 + wn] = pr[tm*2 + 1];
                }
            }
            __syncthreads();
            if (tid < 128) {
                int row = tid, head = row >> 6, d = row & 63;
                float p = pmm[row*2] + pmm[row*2 + 1];
                int bh = blockIdx.z*NHEADS + (m0 >> 6) + head;
                ppart[((size_t)bh*gridDim.x + blockIdx.x)*DHEAD + d] = p;
            }
        }
    } else if (mode == 3) {
        // per-pixel (sum, sumsq) over this CTA's 128 channels
        float* sS = (float*)smem;            // [4 wm][64 c]
        float* sQ = sS + 256;                // [4 wm][64 c]
        int lr = lane >> 2, lc = lane & 3;
        #pragma unroll
        for (int tn = 0; tn < 4; tn++) {
            float s0 = 0.f, q0 = 0.f, s1 = 0.f, q1 = 0.f;
            #pragma unroll
            for (int tm = 0; tm < 2; tm++) {
                s0 += acc[tm][tn][0] + acc[tm][tn][2];
                q0 += acc[tm][tn][0]*acc[tm][tn][0] + acc[tm][tn][2]*acc[tm][tn][2];
                s1 += acc[tm][tn][1] + acc[tm][tn][3];
                q1 += acc[tm][tn][1]*acc[tm][tn][1] + acc[tm][tn][3]*acc[tm][tn][3];
            }
            #pragma unroll
            for (int off = 4; off <= 16; off <<= 1) {
                s0 += __shfl_xor_sync(~0u, s0, off); q0 += __shfl_xor_sync(~0u, q0, off);
                s1 += __shfl_xor_sync(~0u, s1, off); q1 += __shfl_xor_sync(~0u, q1, off);
            }
            if (lr == 0) {
                int c = wn*32 + tn*8 + lc*2;
                sS[wm*64 + c]     = s0;  sS[wm*64 + c + 1] = s1;
                sQ[wm*64 + c]     = q0;  sQ[wm*64 + c + 1] = q1;
            }
        }
        __syncthreads();
        if (tid < 64) {
            float s = sS[tid] + sS[64 + tid] + sS[128 + tid] + sS[192 + tid];
            float q = sQ[tid] + sQ[64 + tid] + sQ[128 + tid] + sQ[192 + tid];
            ((float2*)auxinv)[((size_t)blockIdx.z*2 + blockIdx.y)*N + n0 + tid] =
                make_float2(s, q);
        }
    }
}

__global__ void probe_reduce_k(const float* __restrict__ part, float* __restrict__ probe) {
    int bh = blockIdx.x, d = threadIdx.x;
    float s = 0.f;
    for (int i = 0; i < NPB; i++) s += part[((size_t)bh*NPB + i)*DHEAD + d];
    probe[bh*DHEAD + d] = s;
}

// ---------------- combine out-proj partials into per-pixel (mean, rstd) ----------------
__global__ void ostat_k(const float2* __restrict__ part, float2* __restrict__ st) {
    int i = blockIdx.x*256 + threadIdx.x;   // over BATCH*NPIX
    int b = i / NPIX, px = i % NPIX;
    float2 p0 = part[((size_t)b*2)*NPIX + px];
    float2 p1 = part[((size_t)b*2 + 1)*NPIX + px];
    float s = p0.x + p1.x, q = p0.y + p1.y;
    float mean = s*(1.f/CDIM);
    float rstd = rsqrtf(q*(1.f/CDIM) - mean*mean + EPS);
    st[i] = make_float2(mean, rstd);
}

// ---------------- row/col |k| sums ----------------
__global__ void rowcol_k(const float* __restrict__ k, const float* __restrict__ kinv,
                         float* __restrict__ rowsum, float* __restrict__ colsum) {
    int d = blockIdx.x, bh = blockIdx.y, t = threadIdx.x; // 64 threads
    __shared__ float s[64*65];
    const float* base = k + ((size_t)bh*DHEAD + d)*CPIX;
    const float* inv  = kinv + (size_t)bh*CPIX;
    #pragma unroll 8
    for (int h = 0; h < 64; h++) {
        int px = h*64 + t;
        s[h*65 + t] = fabsf(base[px]) * inv[px];
    }
    __syncthreads();
    float rs = 0.f, cs = 0.f;
    #pragma unroll 8
    for (int w = 0; w < 64; w++) rs += s[t*65 + w];
    #pragma unroll 8
    for (int h = 0; h < 64; h++) cs += s[h*65 + t];
    rowsum[((size_t)bh*DHEAD + d)*HC + t] = rs;
    colsum[((size_t)bh*DHEAD + d)*WC + t] = cs;
}

// ---------------- scores + exact top-8 (first index wins ties) ----------------
__global__ void topk_k(const float* __restrict__ probe, const float* __restrict__ rowsum,
                       const float* __restrict__ colsum, int* __restrict__ topidx) {
    int bh = blockIdx.x, t = threadIdx.x; // 64 threads
    __shared__ float sr[64], sc[64];
    __shared__ int th[8], tw[8];
    float r = 0.f, c = 0.f;
    for (int d = 0; d < DHEAD; d++) {
        float p = probe[bh*DHEAD + d];
        r += p * rowsum[((size_t)bh*DHEAD + d)*HC + t];
        c += p * colsum[((size_t)bh*DHEAD + d)*WC + t];
    }
    sr[t] = r; sc[t] = c;
    __syncthreads();
    if (t == 0) {
        bool used[64];
        for (int i = 0; i < 64; i++) used[i] = false;
        for (int i = 0; i < 8; i++) {
            float best = -1e38f; int bi = 0;
            for (int h = 0; h < 64; h++)
                if (!used[h] && sr[h] > best) { best = sr[h]; bi = h; }
            used[bi] = true; th[i] = bi;
        }
        for (int i = 0; i < 64; i++) used[i] = false;
        for (int i = 0; i < 8; i++) {
            float best = -1e38f; int bi = 0;
            for (int w = 0; w < 64; w++)
                if (!used[w] && sc[w] > best) { best = sc[w]; bi = w; }
            used[bi] = true; tw[i] = bi;
        }
        for (int i = 0; i < 8; i++)
            for (int j = 0; j < 8; j++)
                topidx[bh*NKV + i*8 + j] = th[i]*WC + tw[j];
    }
}

// ---------------- pack: K split [j][d]; V at pruned px split [d][j] ----------------
__global__ void pack_k(const float* __restrict__ k, const float* __restrict__ kinv,
                       const float* __restrict__ ctx_raw, const float2* __restrict__ cstat,
                       const float* __restrict__ cg, const float* __restrict__ cb_,
                       const float* __restrict__ wkv, const int* __restrict__ topidx,
                       __nv_bfloat16* __restrict__ kh, __nv_bfloat16* __restrict__ kl,
                       __nv_bfloat16* __restrict__ vh, __nv_bfloat16* __restrict__ vl) {
    extern __shared__ float ctx_s[];   // [c][j]
    __shared__ int pos[NKV];
    __shared__ float2 stj[NKV];
    int bh = blockIdx.x, b = bh >> 3, h = bh & 7;
    int tid = threadIdx.x;
    if (tid < NKV) {
        int p = topidx[bh*NKV + tid];
        pos[tid] = p;
        stj[tid] = cstat[(size_t)b*CPIX + p];
    }
    __syncthreads();

    int j = tid & 63, c0 = tid >> 6;
    float2 st = stj[j];
    for (int cc = 0; cc < 64; cc++) {
        int c = cc*4 + c0;
        float raw = ctx_raw[((size_t)b*CDIM + c)*CPIX + pos[j]];
        ctx_s[c*64 + j] = (raw - st.x)*st.y*cg[c] + cb_[c];
    }

    #pragma unroll
    for (int i = 0; i < 16; i++) {
        int idx = tid + i*256;
        int jj = idx >> 6, d = idx & 63;
        int p = pos[jj];
        float kv = k[((size_t)bh*DHEAD + d)*CPIX + p] * kinv[(size_t)bh*CPIX + p];
        __nv_bfloat16 hh, ll;
        split1(kv, hh, ll);
        kh[(size_t)bh*NKV*DHEAD + idx] = hh;
        kl[(size_t)bh*NKV*DHEAD + idx] = ll;
    }
    __syncthreads();

    for (int dd = 0; dd < 16; dd++) {
        int d = dd*4 + c0;
        const float* wr = wkv + ((size_t)(INNER + h*DHEAD + d))*CDIM;
        float acc = 0.f;
        #pragma unroll 8
        for (int c = 0; c < CDIM; c++) acc += wr[c] * ctx_s[c*64 + j];
        __nv_bfloat16 hh, ll;
        split1(acc, hh, ll);
        vh[(size_t)bh*NKV*DHEAD + d*64 + j] = hh;
        vl[(size_t)bh*NKV*DHEAD + d*64 + j] = ll;
    }
}

// ---------------- fused HMMA attention: in-register softmax, no P array ----------------
#define AQ_TERM 18432                     // 128*RSB
#define AK_TERM 9216                      // 64*RSB
#define ATTN_SMEM (2*AQ_TERM + 2*AK_TERM)   // 55296
__global__ void __launch_bounds__(256)
attn_k(const float* __restrict__ qb_all, const float* __restrict__ qinv_all,
       const __nv_bfloat16* __restrict__ kh_all, const __nv_bfloat16* __restrict__ kl_all,
       const __nv_bfloat16* __restrict__ vh_all, const __nv_bfloat16* __restrict__ vl_all,
       float* __restrict__ attno) {
    extern __shared__ char smem[];
    char* Qh = smem;                        // [px][RS]  (later Ph/Pl, then Os)
    char* Ql = smem + AQ_TERM;
    char* Kh = smem + 2*AQ_TERM;            // [j][RS] (later V [d][RS])
    char* Kl = smem + 2*AQ_TERM + AK_TERM;
    __shared__ float qiv[128];
    __shared__ float red[128][2];
    uint32_t qBase = smem_u32(Qh);
    uint32_t kBase = smem_u32(Kh);

    int bh = blockIdx.y;
    int px0 = blockIdx.x * 128;
    int tid = threadIdx.x, lane = tid & 31, wid = tid >> 5;
    int wm = wid & 3, wn = wid >> 2;
    int lr = lane >> 2, lc = lane & 3;

    const float* qb = qb_all + (size_t)bh*DHEAD*NPIX + px0;
    const float* qi = qinv_all + (size_t)bh*NPIX + px0;
    const uint32_t* khp = (const uint32_t*)(kh_all + (size_t)bh*NKV*DHEAD);
    const uint32_t* klp = (const uint32_t*)(kl_all + (size_t)bh*NKV*DHEAD);
    const uint32_t* vhp = (const uint32_t*)(vh_all + (size_t)bh*NKV*DHEAD);
    const uint32_t* vlp = (const uint32_t*)(vl_all + (size_t)bh*NKV*DHEAD);

    uint32_t aLane = (uint32_t)((wm*32 + ((lane>>3)&1)*8 + (lane&7))*RSB + (lane>>4)*16);
    uint32_t bLane = (uint32_t)(((lane>>4)*8 + (lane&7))*RSB + ((lane>>3)&1)*16 + wn*32*RSB);

    if (tid < 128) qiv[tid] = qi[tid];
    for (int i = tid; i < 2048; i += 256) {
        int j = i >> 5, dp = i & 31;
        ((uint32_t*)(Kh + j*RSB))[dp] = khp[i];
        ((uint32_t*)(Kl + j*RSB))[dp] = klp[i];
    }
    __syncthreads();
    #pragma unroll
    for (int it = 0; it < 16; it++) {
        int idx = tid + it*256;
        int p  = (idx & 7) | (((idx >> 5) & 15) << 3);
        int dp = ((idx >> 3) & 3) | ((idx >> 9) << 2);
        float iv = qiv[p];
        float v0 = qb[(size_t)(2*dp)*NPIX + p] * iv;
        float v1 = qb[(size_t)(2*dp+1)*NPIX + p] * iv;
        uint32_t hi, lo;
        split2(v0, v1, hi, lo);
        ((uint32_t*)(Qh + p*RSB))[dp] = hi;
        ((uint32_t*)(Ql + p*RSB))[dp] = lo;
    }
    __syncthreads();

    // QK^T -> acc (registers)
    float acc[2][4][4];
    #pragma unroll
    for (int i = 0; i < 2; i++)
        #pragma unroll
        for (int j = 0; j < 4; j++)
            #pragma unroll
            for (int l = 0; l < 4; l++) acc[i][j][l] = 0.f;
    #pragma unroll
    for (int kk = 0; kk < 4; kk++) {
        uint32_t af[2][2][4], bfr[2][4][2];
        #pragma unroll
        for (int t = 0; t < 2; t++) {
            #pragma unroll
            for (int tm = 0; tm < 2; tm++)
                ldsm_x4(af[t][tm], qBase + t*AQ_TERM + tm*16*RSB + kk*32 + aLane);
            #pragma unroll
            for (int pr = 0; pr < 2; pr++) {
                uint32_t r[4];
                ldsm_x4(r, kBase + t*AK_TERM + pr*16*RSB + kk*32 + bLane);
                bfr[t][pr*2][0]   = r[0]; bfr[t][pr*2][1]   = r[1];
                bfr[t][pr*2+1][0] = r[2]; bfr[t][pr*2+1][1] = r[3];
            }
        }
        #pragma unroll
        for (int tm = 0; tm < 2; tm++)
            #pragma unroll
            for (int tn = 0; tn < 4; tn++) {
                mma_bf16(acc[tm][tn], af[0][tm], bfr[0][tn]);
                mma_bf16(acc[tm][tn], af[0][tm], bfr[1][tn]);
                mma_bf16(acc[tm][tn], af[1][tm], bfr[0][tn]);
            }
    }
    __syncthreads();   // all K/Q smem reads done

    // stage V into K region ([d][RS])
    for (int i = tid; i < 2048; i += 256) {
        int d = i >> 5, jp = i & 31;
        ((uint32_t*)(Kh + d*RSB))[jp] = vhp[i];
        ((uint32_t*)(Kl + d*RSB))[jp] = vlp[i];
    }

    // ---- in-register softmax over j ----
    float mrow[2][2];
    #pragma unroll
    for (int tm = 0; tm < 2; tm++) {
        float m0 = -1e30f, m1 = -1e30f;
        #pragma unroll
        for (int tn = 0; tn < 4; tn++) {
            m0 = fmaxf(m0, fmaxf(acc[tm][tn][0], acc[tm][tn][1]));
            m1 = fmaxf(m1, fmaxf(acc[tm][tn][2], acc[tm][tn][3]));
        }
        #pragma unroll
        for (int off = 1; off <= 2; off <<= 1) {
            m0 = fmaxf(m0, __shfl_xor_sync(~0u, m0, off));
            m1 = fmaxf(m1, __shfl_xor_sync(~0u, m1, off));
        }
        mrow[tm][0] = m0; mrow[tm][1] = m1;
    }
    if (lc == 0) {
        #pragma unroll
        for (int tm = 0; tm < 2; tm++) {
            red[wm*32 + tm*16 + lr][wn]     = mrow[tm][0];
            red[wm*32 + tm*16 + lr + 8][wn] = mrow[tm][1];
        }
    }
    __syncthreads();
    float fm[2][2];
    #pragma unroll
    for (int tm = 0; tm < 2; tm++) {
        fm[tm][0] = fmaxf(red[wm*32 + tm*16 + lr][0],     red[wm*32 + tm*16 + lr][1]);
        fm[tm][1] = fmaxf(red[wm*32 + tm*16 + lr + 8][0], red[wm*32 + tm*16 + lr + 8][1]);
    }
    __syncthreads();
    float srow[2][2] = {{0.f,0.f},{0.f,0.f}};
    #pragma unroll
    for (int tm = 0; tm < 2; tm++)
        #pragma unroll
        for (int tn = 0; tn < 4; tn++) {
            acc[tm][tn][0] = expf(acc[tm][tn][0] - fm[tm][0]);
            acc[tm][tn][1] = expf(acc[tm][tn][1] - fm[tm][0]);
            acc[tm][tn][2] = expf(acc[tm][tn][2] - fm[tm][1]);
            acc[tm][tn][3] = expf(acc[tm][tn][3] - fm[tm][1]);
            srow[tm][0] += acc[tm][tn][0] + acc[tm][tn][1];
            srow[tm][1] += acc[tm][tn][2] + acc[tm][tn][3];
        }
    #pragma unroll
    for (int tm = 0; tm < 2; tm++)
        #pragma unroll
        for (int off = 1; off <= 2; off <<= 1) {
            srow[tm][0] += __shfl_xor_sync(~0u, srow[tm][0], off);
            srow[tm][1] += __shfl_xor_sync(~0u, srow[tm][1], off);
        }
    if (lc == 0) {
        #pragma unroll
        for (int tm = 0; tm < 2; tm++) {
            red[wm*32 + tm*16 + lr][wn]     = srow[tm][0];
            red[wm*32 + tm*16 + lr + 8][wn] = srow[tm][1];
        }
    }
    __syncthreads();
    float fs[2][2];
    #pragma unroll
    for (int tm = 0; tm < 2; tm++) {
        fs[tm][0] = 1.f / (red[wm*32 + tm*16 + lr][0]     + red[wm*32 + tm*16 + lr][1]);
        fs[tm][1] = 1.f / (red[wm*32 + tm*16 + lr + 8][0] + red[wm*32 + tm*16 + lr + 8][1]);
    }

    // scale + split directly into Qh/Ql as P tiles [r][j]
    #pragma unroll
    for (int tm = 0; tm < 2; tm++)
        #pragma unroll
        for (int tn = 0; tn < 4; tn++) {
            int r1 = wm*32 + tm*16 + lr;
            int cw = wn*16 + tn*4 + lc;   // uint32 index = col/2
            float p0 = acc[tm][tn][0] * fs[tm][0];
            float p1 = acc[tm][tn][1] * fs[tm][0];
            float p2 = acc[tm][tn][2] * fs[tm][1];
            float p3 = acc[tm][tn][3] * fs[tm][1];
            uint32_t hi, lo;
            split2(p0, p1, hi, lo);
            ((uint32_t*)(Qh + r1*RSB))[cw] = hi;
            ((uint32_t*)(Ql + r1*RSB))[cw] = lo;
            split2(p2, p3, hi, lo);
            ((uint32_t*)(Qh + (r1+8)*RSB))[cw] = hi;
            ((uint32_t*)(Ql + (r1+8)*RSB))[cw] = lo;
        }
    __syncthreads();

    // P @ V -> out[px][d]
    {
        float acc2[2][4][4];
        #pragma unroll
        for (int i = 0; i < 2; i++)
            #pragma unroll
            for (int j = 0; j < 4; j++)
                #pragma unroll
                for (int l = 0; l < 4; l++) acc2[i][j][l] = 0.f;
        #pragma unroll
        for (int kk = 0; kk < 4; kk++) {
            uint32_t af[2][2][4], bfr[2][4][2];
            #pragma unroll
            for (int t = 0; t < 2; t++) {
                #pragma unroll
                for (int tm = 0; tm < 2; tm++)
                    ldsm_x4(af[t][tm], qBase + t*AQ_TERM + tm*16*RSB + kk*32 + aLane);
                #pragma unroll
                for (int pr = 0; pr < 2; pr++) {
                    uint32_t r[4];
                    ldsm_x4(r, kBase + t*AK_TERM + pr*16*RSB + kk*32 + bLane);
                    bfr[t][pr*2][0]   = r[0]; bfr[t][pr*2][1]   = r[1];
                    bfr[t][pr*2+1][0] = r[2]; bfr[t][pr*2+1][1] = r[3];
                }
            }
            #pragma unroll
            for (int tm = 0; tm < 2; tm++)
                #pragma unroll
                for (int tn = 0; tn < 4; tn++) {
                    mma_bf16(acc2[tm][tn], af[0][tm], bfr[0][tn]);
                    mma_bf16(acc2[tm][tn], af[0][tm], bfr[1][tn]);
                    mma_bf16(acc2[tm][tn], af[1][tm], bfr[0][tn]);
                }
        }
        __syncthreads();   // P/V reads done; reuse Qh/Ql region as Os [64][132] fp32
        float* Os = (float*)Qh;
        #pragma unroll
        for (int tm = 0; tm < 2; tm++)
            #pragma unroll
            for (int tn = 0; tn < 4; tn++) {
                int r = wm*32 + tm*16 + lr;
                int c = wn*32 + tn*8 + lc*2;
                Os[c*132 + r]       = acc2[tm][tn][0];
                Os[(c+1)*132 + r]   = acc2[tm][tn][1];
                Os[c*132 + r + 8]   = acc2[tm][tn][2];
                Os[(c+1)*132 + r+8] = acc2[tm][tn][3];
            }
        __syncthreads();
        float* ob = attno + (size_t)bh*DHEAD*NPIX + px0;
        for (int i = tid; i < 8192; i += 256) {
            int d = i >> 7, p = i & 127;
            ob[(size_t)d*NPIX + p] = Os[d*132 + p];
        }
    }
}

// ---------------- final single-pass: normalize(obuf) with precomputed stats + residual ----------------
__global__ void final1_k(const float* __restrict__ x, const float2* __restrict__ st,
                         const float* __restrict__ g, const float* __restrict__ bb,
                         const float* __restrict__ gamma, const float* __restrict__ resid,
                         float* __restrict__ y) {
    int i = blockIdx.x*256 + threadIdx.x;    // float4 index over [b][c][px]
    int px4 = i % (NPIX/4);
    int rest = i / (NPIX/4);
    int c = rest % CDIM, b = rest / CDIM;
    const float4* stp = (const float4*)&st[(size_t)b*NPIX + px4*4];
    float4 s01 = stp[0], s23 = stp[1];       // (m0,r0,m1,r1), (m2,r2,m3,r3)
    float4 v  = ((const float4*)x)[i];
    float4 rr = ((const float4*)resid)[i];
    float gg = g[c], bv = bb[c], gm = gamma[0];
    float4 o;
    o.x = gm*((v.x - s01.x)*s01.y*gg + bv) + rr.x;
    o.y = gm*((v.y - s01.z)*s01.w*gg + bv) + rr.y;
    o.z = gm*((v.z - s23.x)*s23.y*gg + bv) + rr.z;
    o.w = gm*((v.w - s23.z)*s23.w*gg + bv) + rr.w;
    ((float4*)y)[i] = o;
}

// ---------------- launch ----------------
extern "C" void kernel_launch(void* const* d_in, const int* in_sizes, int n_in,
                              void* d_out, int out_size) {
    const float* query_source = (const float*)d_in[0];
    const float* context      = (const float*)d_in[1];
    const float* qs_g  = (const float*)d_in[2];
    const float* qs_b  = (const float*)d_in[3];
    const float* ctx_g = (const float*)d_in[4];
    const float* ctx_b = (const float*)d_in[5];
    const float* out_g = (const float*)d_in[6];
    const float* out_b = (const float*)d_in[7];
    const float* w_q   = (const float*)d_in[8];
    const float* w_kv  = (const float*)d_in[9];
    const float* w_out = (const float*)d_in[10];
    const float* gamma = (const float*)d_in[11];
    float* out = (float*)d_out;

    float *qb, *kb, *attno, *obuf, *qinv, *kinv, *ppart, *probe, *rowsum, *colsum;
    int* topidx;
    float2 *cstat, *qstat, *opart, *ostat;
    __nv_bfloat16 *kh, *kl, *vh, *vl, *wqh, *wql, *wkh, *wkl, *woh, *wol;
    cudaGetSymbolAddress((void**)&qb,    g_q);
    cudaGetSymbolAddress((void**)&kb,    g_k);
    cudaGetSymbolAddress((void**)&attno, g_attno);
    cudaGetSymbolAddress((void**)&obuf,  g_obuf);
    cudaGetSymbolAddress((void**)&qinv,  g_qinv);
    cudaGetSymbolAddress((void**)&kinv,  g_kinv);
    cudaGetSymbolAddress((void**)&ppart, g_probe_part);
    cudaGetSymbolAddress((void**)&probe, g_probe);
    cudaGetSymbolAddress((void**)&rowsum,g_rowsum);
    cudaGetSymbolAddress((void**)&colsum,g_colsum);
    cudaGetSymbolAddress((void**)&topidx,g_topidx);
    cudaGetSymbolAddress((void**)&cstat, g_ctx_stat);
    cudaGetSymbolAddress((void**)&qstat, g_qs_stat);
    cudaGetSymbolAddress((void**)&opart, g_opart);
    cudaGetSymbolAddress((void**)&ostat, g_ostat);
    cudaGetSymbolAddress((void**)&kh,    g_kh);
    cudaGetSymbolAddress((void**)&kl,    g_kl);
    cudaGetSymbolAddress((void**)&vh,    g_vh);
    cudaGetSymbolAddress((void**)&vl,    g_vl);
    cudaGetSymbolAddress((void**)&wqh,   g_wq_h);
    cudaGetSymbolAddress((void**)&wql,   g_wq_l);
    cudaGetSymbolAddress((void**)&wkh,   g_wk_h);
    cudaGetSymbolAddress((void**)&wkl,   g_wk_l);
    cudaGetSymbolAddress((void**)&woh,   g_wo_h);
    cudaGetSymbolAddress((void**)&wol,   g_wo_l);

    cudaFuncSetAttribute(hmma_gemm_k, cudaFuncAttributeMaxDynamicSharedMemorySize, GEMM_SMEM);
    cudaFuncSetAttribute(attn_k, cudaFuncAttributeMaxDynamicSharedMemorySize, ATTN_SMEM);
    cudaFuncSetAttribute(pack_k, cudaFuncAttributeMaxDynamicSharedMemorySize, 256*64*4);

    // 0) weight splits (tiny)
    split_w_k<<<(INNER*CDIM/4 + 255)/256, 256>>>(w_q,   wqh, wql, INNER*CDIM);
    split_w_k<<<(INNER*CDIM/4 + 255)/256, 256>>>(w_kv,  wkh, wkl, INNER*CDIM);  // K half
    split_w_k<<<(CDIM*INNER/4 + 255)/256, 256>>>(w_out, woh, wol, CDIM*INNER);

    // 1) per-pixel layernorm stats (128 px/block, c-split-8)
    stat_k<<<dim3(CPIX/128, BATCH), 256>>>(context, cstat, CPIX);
    stat_k<<<dim3(NPIX/128, BATCH), 256>>>(query_source, qstat, NPIX);

    // 2) projections with fused inv/probe epilogues
    hmma_gemm_k<<<dim3(CPIX/64, INNER/128, BATCH), 256, GEMM_SMEM>>>(
        wkh, wkl, context, cstat, ctx_g, ctx_b, kb, INNER, CPIX, CDIM,
        (long)CDIM*CPIX, (long)INNER*CPIX, 2, kinv, nullptr);
    hmma_gemm_k<<<dim3(NPIX/64, INNER/128, BATCH), 256, GEMM_SMEM>>>(
        wqh, wql, query_source, qstat, qs_g, qs_b, qb, INNER, NPIX, CDIM,
        (long)CDIM*NPIX, (long)INNER*NPIX, 1, qinv, ppart);

    // 3) probe + pruning scores
    probe_reduce_k<<<BH, DHEAD>>>(ppart, probe);
    rowcol_k<<<dim3(DHEAD, BH), 64>>>(kb, kinv, rowsum, colsum);
    topk_k<<<BH, 64>>>(probe, rowsum, colsum, topidx);

    // 4) pack pruned K (split) + compute pruned V (split, transposed)
    pack_k<<<BH, 256, 256*64*4>>>(kb, kinv, context, cstat, ctx_g, ctx_b,
                                  w_kv, topidx, kh, kl, vh, vl);

    // 5) fused HMMA attention (in-register softmax)
    attn_k<<<dim3(NPIX/128, BH), 256, ATTN_SMEM>>>(qb, qinv, kh, kl, vh, vl, attno);

    // 6) output projection with fused per-pixel sum/sumsq epilogue (mode 3)
    hmma_gemm_k<<<dim3(NPIX/64, CDIM/128, BATCH), 256, GEMM_SMEM>>>(
        woh, wol, attno, nullptr, nullptr, nullptr, obuf, CDIM, NPIX, INNER,
        (long)INNER*NPIX, (long)CDIM*NPIX, 3, (float*)opart, nullptr);

    // 6b) combine partials -> per-pixel (mean, rstd)
    ostat_k<<<(BATCH*NPIX)/256, 256>>>(opart, ostat);

    // 7) final single-pass norm + gamma + residual
    final1_k<<<(BATCH*CDIM*NPIX/4)/256, 256>>>(obuf, ostat, out_g, out_b, gamma,
                                               query_source, out);
}

// round 17
// speedup vs baseline: 1.1195x; 1.0513x over previous
#include <cuda_runtime.h>
#include <cuda_bf16.h>
#include <math.h>
#include <stdint.h>

// ---------------- problem dims ----------------
#define BATCH   8
#define CDIM    256
#define INNER   512
#define NHEADS  8
#define DHEAD   64
#define HQ      96
#define WQ      96
#define NPIX    (HQ*WQ)     // 9216
#define HC      64
#define WC      64
#define CPIX    (HC*WC)     // 4096
#define BH      (BATCH*NHEADS) // 64
#define NKV     64          // 8x8 pruned
#define EPS     1e-5f
#define NPB     (NPIX/64)   // 144 probe partial blocks per bh
#define NKT     (CPIX/64)   // 64 k-proj n-tiles

// ---------------- scratch (static device memory; no allocs) ----------------
__device__ float  g_q    [BATCH*INNER*NPIX];   // normalized q [bh][d][px]
__device__ float  g_k    [BATCH*INNER*CPIX];   // normalized k [bh][d][px]
__device__ float  g_attno[BATCH*INNER*NPIX];   // attention out [bh][d][px]
__device__ float  g_obuf [BATCH*CDIM*NPIX];
__device__ float  g_probe_part[BH*NPB*DHEAD];
__device__ float  g_probe[BH*DHEAD];
__device__ float  g_rowsum[BH*DHEAD*HC];
__device__ float  g_colsum[BH*DHEAD*WC];
__device__ int    g_topidx[BH*NKV];
__device__ float2 g_ctx_stat[BATCH*CPIX];
__device__ float2 g_qs_stat [BATCH*NPIX];
__device__ float2 g_opart[BATCH*2*NPIX];       // per-pixel (sum, sumsq) partials
__device__ float2 g_ostat[BATCH*NPIX];         // per-pixel (mean, rstd)
__device__ __nv_bfloat16 g_kh[BH*NKV*DHEAD], g_kl[BH*NKV*DHEAD];  // [j][d]
__device__ __nv_bfloat16 g_vh[BH*NKV*DHEAD], g_vl[BH*NKV*DHEAD];  // [d][j]
__device__ __nv_bfloat16 g_wq_h [INNER*CDIM], g_wq_l [INNER*CDIM];
__device__ __nv_bfloat16 g_wk_h [INNER*CDIM], g_wk_l [INNER*CDIM];
__device__ __nv_bfloat16 g_wo_h [CDIM*INNER], g_wo_l [CDIM*INNER];

// ---------------- helpers ----------------
__device__ __forceinline__ uint32_t smem_u32(const void* p) {
    uint32_t a;
    asm("{ .reg .u64 t; cvta.to.shared.u64 t, %1; cvt.u32.u64 %0, t; }" : "=r"(a) : "l"(p));
    return a;
}
__device__ __forceinline__ unsigned short bf_bits(__nv_bfloat16 h) {
    return *reinterpret_cast<unsigned short*>(&h);
}
__device__ __forceinline__ void split1(float v, __nv_bfloat16& h, __nv_bfloat16& l) {
    h = __float2bfloat16(v);
    l = __float2bfloat16(v - __bfloat162float(h));
}
__device__ __forceinline__ void split2(float a, float b, uint32_t& hi, uint32_t& lo) {
    __nv_bfloat16 ha, la, hb, lb;
    split1(a, ha, la); split1(b, hb, lb);
    hi = (uint32_t)bf_bits(ha) | ((uint32_t)bf_bits(hb) << 16);
    lo = (uint32_t)bf_bits(la) | ((uint32_t)bf_bits(lb) << 16);
}
__device__ __forceinline__ void mma_bf16(float* c, const uint32_t* a, const uint32_t* b) {
    asm volatile(
        "mma.sync.aligned.m16n8k16.row.col.f32.bf16.bf16.f32 "
        "{%0,%1,%2,%3}, {%4,%5,%6,%7}, {%8,%9}, {%0,%1,%2,%3};\n"
        : "+f"(c[0]), "+f"(c[1]), "+f"(c[2]), "+f"(c[3])
        : "r"(a[0]), "r"(a[1]), "r"(a[2]), "r"(a[3]), "r"(b[0]), "r"(b[1]));
}
__device__ __forceinline__ void ldsm_x4(uint32_t* r, uint32_t addr) {
    asm volatile("ldmatrix.sync.aligned.m8n8.x4.shared.b16 {%0,%1,%2,%3}, [%4];"
        : "=r"(r[0]), "=r"(r[1]), "=r"(r[2]), "=r"(r[3]) : "r"(addr));
}
__device__ __forceinline__ void ldsm_x4_t(uint32_t* r, uint32_t addr) {
    asm volatile("ldmatrix.sync.aligned.m8n8.x4.trans.shared.b16 {%0,%1,%2,%3}, [%4];"
        : "=r"(r[0]), "=r"(r[1]), "=r"(r[2]), "=r"(r[3]) : "r"(addr));
}

#define RS   72
#define RSB  144

// ---------------- weight hi/lo split ----------------
__global__ void split_w_k(const float* __restrict__ src, __nv_bfloat16* __restrict__ dh,
                          __nv_bfloat16* __restrict__ dl, int n) {
    int i = blockIdx.x*256 + threadIdx.x;
    if (i*4 < n) {
        float4 v = *(const float4*)&src[i*4];
        uint32_t h01, l01, h23, l23;
        split2(v.x, v.y, h01, l01);
        split2(v.z, v.w, h23, l23);
        *(uint2*)&dh[i*4] = make_uint2(h01, h23);
        *(uint2*)&dl[i*4] = make_uint2(l01, l23);
    }
}

// ---------------- per-pixel layernorm stats (float4 + c-split-8, 128 px/block) ----------------
__global__ void stat_k(const float* __restrict__ x, float2* __restrict__ st, int HW) {
    int tid = threadIdx.x;
    int cs = tid & 7, pg = blockIdx.x*32 + (tid >> 3);
    int b  = blockIdx.y;
    const float4* xb = (const float4*)(x + (size_t)b*CDIM*HW) + pg;
    int c0 = cs*32, hw4 = HW >> 2;
    float4 s = {0,0,0,0}, s2 = {0,0,0,0};
    #pragma unroll 16
    for (int i = 0; i < 32; i++) {
        float4 v = xb[(size_t)(c0+i)*hw4];
        s.x += v.x; s.y += v.y; s.z += v.z; s.w += v.w;
        s2.x += v.x*v.x; s2.y += v.y*v.y; s2.z += v.z*v.z; s2.w += v.w*v.w;
    }
    #pragma unroll
    for (int off = 1; off <= 4; off <<= 1) {
        s.x += __shfl_xor_sync(~0u, s.x, off);  s.y += __shfl_xor_sync(~0u, s.y, off);
        s.z += __shfl_xor_sync(~0u, s.z, off);  s.w += __shfl_xor_sync(~0u, s.w, off);
        s2.x += __shfl_xor_sync(~0u, s2.x, off); s2.y += __shfl_xor_sync(~0u, s2.y, off);
        s2.z += __shfl_xor_sync(~0u, s2.z, off); s2.w += __shfl_xor_sync(~0u, s2.w, off);
    }
    if (cs == 0) {
        float m0 = s.x*(1.f/CDIM), m1 = s.y*(1.f/CDIM), m2 = s.z*(1.f/CDIM), m3 = s.w*(1.f/CDIM);
        float r0 = rsqrtf(s2.x*(1.f/CDIM) - m0*m0 + EPS);
        float r1 = rsqrtf(s2.y*(1.f/CDIM) - m1*m1 + EPS);
        float r2 = rsqrtf(s2.z*(1.f/CDIM) - m2*m2 + EPS);
        float r3 = rsqrtf(s2.w*(1.f/CDIM) - m3*m3 + EPS);
        float4* dst = (float4*)&st[(size_t)b*HW + pg*4];
        dst[0] = make_float4(m0, r0, m1, r1);
        dst[1] = make_float4(m2, r2, m3, r3);
    }
}

#define A_TERM 18432                      // 128*RSB
#define B_TERM 9216                       // 64*RSB
#define GEMM_SMEM (2*A_TERM + 2*B_TERM)   // 55296

// ---------------- combined q/k projection GEMM, fused norm + L2-normalized store ----------------
// grid: (NKT + NPB, 4, BATCH). x < NKT -> k-proj, else q-proj.
__global__ void __launch_bounds__(256, 2)
proj_gemm_k(const __nv_bfloat16* __restrict__ WhK, const __nv_bfloat16* __restrict__ WlK,
            const __nv_bfloat16* __restrict__ WhQ, const __nv_bfloat16* __restrict__ WlQ,
            const float* __restrict__ Xk, const float* __restrict__ Xq,
            const float2* __restrict__ statK, const float2* __restrict__ statQ,
            const float* __restrict__ gK, const float* __restrict__ bK,
            const float* __restrict__ gQ, const float* __restrict__ bQ,
            float* __restrict__ Ck, float* __restrict__ Cq,
            float* __restrict__ ppart) {
    extern __shared__ char smem[];
    char* As0 = smem;
    char* As1 = smem + A_TERM;
    char* Bs0 = smem + 2*A_TERM;
    char* Bs1 = smem + 2*A_TERM + B_TERM;
    uint32_t aBase = smem_u32(As0);
    uint32_t bBase = smem_u32(Bs0);

    int tid = threadIdx.x, lane = tid & 31, wid = tid >> 5;
    int wm = wid & 3, wn = wid >> 2;

    bool isK = blockIdx.x < NKT;
    int tx = isK ? blockIdx.x : blockIdx.x - NKT;
    int N = isK ? CPIX : NPIX;
    const __nv_bfloat16* Wh = isK ? WhK : WhQ;
    const __nv_bfloat16* Wl = isK ? WlK : WlQ;
    const float* Xp = (isK ? Xk : Xq) + (size_t)blockIdx.z*CDIM*N;
    const float2* stat = (isK ? statK : statQ) + (size_t)blockIdx.z*N;
    const float* gvec = isK ? gK : gQ;
    const float* bvec = isK ? bK : bQ;
    float* Cp = (isK ? Ck : Cq) + (size_t)blockIdx.z*INNER*N;

    int n0 = tx * 64, m0 = blockIdx.y * 128;
    const int K = CDIM;

    uint32_t aLane = (uint32_t)((wm*32 + ((lane>>3)&1)*8 + (lane&7))*RSB + (lane>>4)*16);
    uint32_t bLane = (uint32_t)((((lane>>3)&1)*8 + (lane&7))*RSB + (wn*32 + (lane>>4)*8)*2);

    int ngf = tid & 7;
    float2 st8[8];
    {
        const float2* stp = stat + n0 + ngf*8;
        #pragma unroll
        for (int i = 0; i < 8; i++) st8[i] = stp[i];
    }

    float acc[2][4][4];
    #pragma unroll
    for (int i = 0; i < 2; i++)
        #pragma unroll
        for (int j = 0; j < 4; j++)
            #pragma unroll
            for (int l = 0; l < 4; l++) acc[i][j][l] = 0.f;

    int nch = K >> 6;
    for (int ch = 0; ch < nch; ch++) {
        int k0 = ch << 6;
        #pragma unroll
        for (int p = 0; p < 4; p++) {
            int idx = tid + p*256;
            int m = idx >> 3, kg = idx & 7;
            size_t go = (size_t)(m0+m)*K + k0 + kg*8;
            *(uint4*)(As0 + m*RSB + kg*16) = *(const uint4*)&Wh[go];
            *(uint4*)(As1 + m*RSB + kg*16) = *(const uint4*)&Wl[go];
        }
        #pragma unroll
        for (int p = 0; p < 2; p++) {
            int idx = tid + p*256;
            int k = idx >> 3;
            const float* src = &Xp[(size_t)(k0+k)*N + n0 + ngf*8];
            float4 x0 = *(const float4*)src;
            float4 x1 = *(const float4*)(src + 4);
            float gg = gvec[k0+k], bb = bvec[k0+k];
            x0.x = (x0.x - st8[0].x)*st8[0].y*gg + bb;
            x0.y = (x0.y - st8[1].x)*st8[1].y*gg + bb;
            x0.z = (x0.z - st8[2].x)*st8[2].y*gg + bb;
            x0.w = (x0.w - st8[3].x)*st8[3].y*gg + bb;
            x1.x = (x1.x - st8[4].x)*st8[4].y*gg + bb;
            x1.y = (x1.y - st8[5].x)*st8[5].y*gg + bb;
            x1.z = (x1.z - st8[6].x)*st8[6].y*gg + bb;
            x1.w = (x1.w - st8[7].x)*st8[7].y*gg + bb;
            uint32_t h[4], l[4];
            split2(x0.x, x0.y, h[0], l[0]); split2(x0.z, x0.w, h[1], l[1]);
            split2(x1.x, x1.y, h[2], l[2]); split2(x1.z, x1.w, h[3], l[3]);
            *(uint4*)(Bs0 + k*RSB + ngf*16) = make_uint4(h[0], h[1], h[2], h[3]);
            *(uint4*)(Bs1 + k*RSB + ngf*16) = make_uint4(l[0], l[1], l[2], l[3]);
        }
        __syncthreads();

        #pragma unroll
        for (int kk = 0; kk < 4; kk++) {
            uint32_t af[2][2][4], bfr[2][4][2];
            #pragma unroll
            for (int t = 0; t < 2; t++) {
                #pragma unroll
                for (int tm = 0; tm < 2; tm++)
                    ldsm_x4(af[t][tm], aBase + t*A_TERM + tm*16*RSB + kk*32 + aLane);
                #pragma unroll
                for (int pr = 0; pr < 2; pr++) {
                    uint32_t r[4];
                    ldsm_x4_t(r, bBase + t*B_TERM + kk*16*RSB + pr*32 + bLane);
                    bfr[t][pr*2][0]   = r[0]; bfr[t][pr*2][1]   = r[1];
                    bfr[t][pr*2+1][0] = r[2]; bfr[t][pr*2+1][1] = r[3];
                }
            }
            #pragma unroll
            for (int tm = 0; tm < 2; tm++)
                #pragma unroll
                for (int tn = 0; tn < 4; tn++) {
                    mma_bf16(acc[tm][tn], af[0][tm], bfr[0][tn]);
                    mma_bf16(acc[tm][tn], af[0][tm], bfr[1][tn]);
                    mma_bf16(acc[tm][tn], af[1][tm], bfr[0][tn]);
                }
        }
        __syncthreads();
    }

    // ---- epilogue: per-pixel inv L2 norm over each head's 64 rows ----
    float* ssm  = (float*)smem;          // [4 wm][64 c]
    float* invm = ssm + 256;             // [2 head][64 c]
    float* pmm  = invm + 128;            // [128 row][2 wn]
    int lr = lane >> 2, lc = lane & 3;

    #pragma unroll
    for (int tn = 0; tn < 4; tn++) {
        float s0 = 0.f, s1 = 0.f;
        #pragma unroll
        for (int tm = 0; tm < 2; tm++) {
            s0 += acc[tm][tn][0]*acc[tm][tn][0] + acc[tm][tn][2]*acc[tm][tn][2];
            s1 += acc[tm][tn][1]*acc[tm][tn][1] + acc[tm][tn][3]*acc[tm][tn][3];
        }
        #pragma unroll
        for (int off = 4; off <= 16; off <<= 1) {
            s0 += __shfl_xor_sync(~0u, s0, off);
            s1 += __shfl_xor_sync(~0u, s1, off);
        }
        if (lr == 0) {
            int c = wn*32 + tn*8 + lc*2;
            ssm[wm*64 + c]     = s0;
            ssm[wm*64 + c + 1] = s1;
        }
    }
    __syncthreads();
    if (tid < 128) {
        int head = tid >> 6, c = tid & 63;
        float ss = ssm[(head*2)*64 + c] + ssm[(head*2+1)*64 + c];
        invm[head*64 + c] = 1.f / fmaxf(sqrtf(ss), 1e-12f);
    }
    __syncthreads();

    // scale accumulators by per-pixel inv (L2 normalize)
    int headw = wm >> 1;
    #pragma unroll
    for (int tn = 0; tn < 4; tn++) {
        int c = wn*32 + tn*8 + lc*2;
        float i0 = invm[headw*64 + c], i1 = invm[headw*64 + c + 1];
        #pragma unroll
        for (int tm = 0; tm < 2; tm++) {
            acc[tm][tn][0] *= i0; acc[tm][tn][1] *= i1;
            acc[tm][tn][2] *= i0; acc[tm][tn][3] *= i1;
        }
    }

    // store normalized C
    #pragma unroll
    for (int tm = 0; tm < 2; tm++)
        #pragma unroll
        for (int tn = 0; tn < 4; tn++) {
            int r = m0 + wm*32 + tm*16 + lr;
            int c = n0 + wn*32 + tn*8 + lc*2;
            *(float2*)&Cp[(size_t)r*N + c]     = make_float2(acc[tm][tn][0], acc[tm][tn][1]);
            *(float2*)&Cp[(size_t)(r+8)*N + c] = make_float2(acc[tm][tn][2], acc[tm][tn][3]);
        }

    // probe partials (q only): per-row sums of normalized q
    if (!isK) {
        float pr[4] = {0.f, 0.f, 0.f, 0.f};
        #pragma unroll
        for (int tn = 0; tn < 4; tn++)
            #pragma unroll
            for (int tm = 0; tm < 2; tm++) {
                pr[tm*2]     += acc[tm][tn][0] + acc[tm][tn][1];
                pr[tm*2 + 1] += acc[tm][tn][2] + acc[tm][tn][3];
            }
        #pragma unroll
        for (int off = 1; off <= 2; off <<= 1)
            #pragma unroll
            for (int r = 0; r < 4; r++) pr[r] += __shfl_xor_sync(~0u, pr[r], off);
        if (lc == 0) {
            #pragma unroll
            for (int tm = 0; tm < 2; tm++) {
                pmm[(wm*32 + tm*16 + lr)*2 + wn]     = pr[tm*2];
                pmm[(wm*32 + tm*16 + lr + 8)*2 + wn] = pr[tm*2 + 1];
            }
        }
        __syncthreads();
        if (tid < 128) {
            int row = tid, head = row >> 6, d = row & 63;
            float p = pmm[row*2] + pmm[row*2 + 1];
            int bh = blockIdx.z*NHEADS + (m0 >> 6) + head;
            ppart[((size_t)bh*NPB + tx)*DHEAD + d] = p;
        }
    }
}

// ---------------- out-proj GEMM (bf16 W, fp32 X) + per-pixel sum/sumsq epilogue ----------------
__global__ void __launch_bounds__(256, 2)
hmma_gemm_k(const __nv_bfloat16* __restrict__ Wh, const __nv_bfloat16* __restrict__ Wl,
            const float* __restrict__ X, float* __restrict__ C,
            int M, int N, int K, long strideX, long strideC,
            float* __restrict__ opart) {
    extern __shared__ char smem[];
    char* As0 = smem;
    char* As1 = smem + A_TERM;
    char* Bs0 = smem + 2*A_TERM;
    char* Bs1 = smem + 2*A_TERM + B_TERM;
    uint32_t aBase = smem_u32(As0);
    uint32_t bBase = smem_u32(Bs0);

    int tid = threadIdx.x, lane = tid & 31, wid = tid >> 5;
    int wm = wid & 3, wn = wid >> 2;
    int n0 = blockIdx.x * 64, m0 = blockIdx.y * 128;
    const float* Xp = X + (size_t)blockIdx.z * strideX;
    float* Cp = C + (size_t)blockIdx.z * strideC;

    uint32_t aLane = (uint32_t)((wm*32 + ((lane>>3)&1)*8 + (lane&7))*RSB + (lane>>4)*16);
    uint32_t bLane = (uint32_t)((((lane>>3)&1)*8 + (lane&7))*RSB + (wn*32 + (lane>>4)*8)*2);

    int ngf = tid & 7;
    float acc[2][4][4];
    #pragma unroll
    for (int i = 0; i < 2; i++)
        #pragma unroll
        for (int j = 0; j < 4; j++)
            #pragma unroll
            for (int l = 0; l < 4; l++) acc[i][j][l] = 0.f;

    int nch = K >> 6;
    for (int ch = 0; ch < nch; ch++) {
        int k0 = ch << 6;
        #pragma unroll
        for (int p = 0; p < 4; p++) {
            int idx = tid + p*256;
            int m = idx >> 3, kg = idx & 7;
            size_t go = (size_t)(m0+m)*K + k0 + kg*8;
            *(uint4*)(As0 + m*RSB + kg*16) = *(const uint4*)&Wh[go];
            *(uint4*)(As1 + m*RSB + kg*16) = *(const uint4*)&Wl[go];
        }
        #pragma unroll
        for (int p = 0; p < 2; p++) {
            int idx = tid + p*256;
            int k = idx >> 3;
            const float* src = &Xp[(size_t)(k0+k)*N + n0 + ngf*8];
            float4 x0 = *(const float4*)src;
            float4 x1 = *(const float4*)(src + 4);
            uint32_t h[4], l[4];
            split2(x0.x, x0.y, h[0], l[0]); split2(x0.z, x0.w, h[1], l[1]);
            split2(x1.x, x1.y, h[2], l[2]); split2(x1.z, x1.w, h[3], l[3]);
            *(uint4*)(Bs0 + k*RSB + ngf*16) = make_uint4(h[0], h[1], h[2], h[3]);
            *(uint4*)(Bs1 + k*RSB + ngf*16) = make_uint4(l[0], l[1], l[2], l[3]);
        }
        __syncthreads();

        #pragma unroll
        for (int kk = 0; kk < 4; kk++) {
            uint32_t af[2][2][4], bfr[2][4][2];
            #pragma unroll
            for (int t = 0; t < 2; t++) {
                #pragma unroll
                for (int tm = 0; tm < 2; tm++)
                    ldsm_x4(af[t][tm], aBase + t*A_TERM + tm*16*RSB + kk*32 + aLane);
                #pragma unroll
                for (int pr = 0; pr < 2; pr++) {
                    uint32_t r[4];
                    ldsm_x4_t(r, bBase + t*B_TERM + kk*16*RSB + pr*32 + bLane);
                    bfr[t][pr*2][0]   = r[0]; bfr[t][pr*2][1]   = r[1];
                    bfr[t][pr*2+1][0] = r[2]; bfr[t][pr*2+1][1] = r[3];
                }
            }
            #pragma unroll
            for (int tm = 0; tm < 2; tm++)
                #pragma unroll
                for (int tn = 0; tn < 4; tn++) {
                    mma_bf16(acc[tm][tn], af[0][tm], bfr[0][tn]);
                    mma_bf16(acc[tm][tn], af[0][tm], bfr[1][tn]);
                    mma_bf16(acc[tm][tn], af[1][tm], bfr[0][tn]);
                }
        }
        __syncthreads();
    }

    // store C
    #pragma unroll
    for (int tm = 0; tm < 2; tm++)
        #pragma unroll
        for (int tn = 0; tn < 4; tn++) {
            int r = m0 + wm*32 + tm*16 + (lane >> 2);
            int c = n0 + wn*32 + tn*8 + (lane & 3)*2;
            *(float2*)&Cp[(size_t)r*N + c]     = make_float2(acc[tm][tn][0], acc[tm][tn][1]);
            *(float2*)&Cp[(size_t)(r+8)*N + c] = make_float2(acc[tm][tn][2], acc[tm][tn][3]);
        }

    // per-pixel (sum, sumsq) over this CTA's 128 channels
    {
        float* sS = (float*)smem;            // [4 wm][64 c]
        float* sQ = sS + 256;                // [4 wm][64 c]
        int lr = lane >> 2, lc = lane & 3;
        #pragma unroll
        for (int tn = 0; tn < 4; tn++) {
            float s0 = 0.f, q0 = 0.f, s1 = 0.f, q1 = 0.f;
            #pragma unroll
            for (int tm = 0; tm < 2; tm++) {
                s0 += acc[tm][tn][0] + acc[tm][tn][2];
                q0 += acc[tm][tn][0]*acc[tm][tn][0] + acc[tm][tn][2]*acc[tm][tn][2];
                s1 += acc[tm][tn][1] + acc[tm][tn][3];
                q1 += acc[tm][tn][1]*acc[tm][tn][1] + acc[tm][tn][3]*acc[tm][tn][3];
            }
            #pragma unroll
            for (int off = 4; off <= 16; off <<= 1) {
                s0 += __shfl_xor_sync(~0u, s0, off); q0 += __shfl_xor_sync(~0u, q0, off);
                s1 += __shfl_xor_sync(~0u, s1, off); q1 += __shfl_xor_sync(~0u, q1, off);
            }
            if (lr == 0) {
                int c = wn*32 + tn*8 + lc*2;
                sS[wm*64 + c]     = s0;  sS[wm*64 + c + 1] = s1;
                sQ[wm*64 + c]     = q0;  sQ[wm*64 + c + 1] = q1;
            }
        }
        __syncthreads();
        if (tid < 64) {
            float s = sS[tid] + sS[64 + tid] + sS[128 + tid] + sS[192 + tid];
            float q = sQ[tid] + sQ[64 + tid] + sQ[128 + tid] + sQ[192 + tid];
            ((float2*)opart)[((size_t)blockIdx.z*2 + blockIdx.y)*N + n0 + tid] =
                make_float2(s, q);
        }
    }
}

__global__ void probe_reduce_k(const float* __restrict__ part, float* __restrict__ probe) {
    int bh = blockIdx.x, d = threadIdx.x;
    float s = 0.f;
    for (int i = 0; i < NPB; i++) s += part[((size_t)bh*NPB + i)*DHEAD + d];
    probe[bh*DHEAD + d] = s;
}

// ---------------- combine out-proj partials into per-pixel (mean, rstd) ----------------
__global__ void ostat_k(const float2* __restrict__ part, float2* __restrict__ st) {
    int i = blockIdx.x*256 + threadIdx.x;
    int b = i / NPIX, px = i % NPIX;
    float2 p0 = part[((size_t)b*2)*NPIX + px];
    float2 p1 = part[((size_t)b*2 + 1)*NPIX + px];
    float s = p0.x + p1.x, q = p0.y + p1.y;
    float mean = s*(1.f/CDIM);
    float rstd = rsqrtf(q*(1.f/CDIM) - mean*mean + EPS);
    st[i] = make_float2(mean, rstd);
}

// ---------------- row/col |k| sums (k pre-normalized) ----------------
__global__ void rowcol_k(const float* __restrict__ k,
                         float* __restrict__ rowsum, float* __restrict__ colsum) {
    int d = blockIdx.x, bh = blockIdx.y, t = threadIdx.x; // 64 threads
    __shared__ float s[64*65];
    const float* base = k + ((size_t)bh*DHEAD + d)*CPIX;
    #pragma unroll 8
    for (int h = 0; h < 64; h++) {
        s[h*65 + t] = fabsf(base[h*64 + t]);
    }
    __syncthreads();
    float rs = 0.f, cs = 0.f;
    #pragma unroll 8
    for (int w = 0; w < 64; w++) rs += s[t*65 + w];
    #pragma unroll 8
    for (int h = 0; h < 64; h++) cs += s[h*65 + t];
    rowsum[((size_t)bh*DHEAD + d)*HC + t] = rs;
    colsum[((size_t)bh*DHEAD + d)*WC + t] = cs;
}

// ---------------- scores + exact top-8 (first index wins ties) ----------------
__global__ void topk_k(const float* __restrict__ probe, const float* __restrict__ rowsum,
                       const float* __restrict__ colsum, int* __restrict__ topidx) {
    int bh = blockIdx.x, t = threadIdx.x; // 64 threads
    __shared__ float sr[64], sc[64];
    __shared__ int th[8], tw[8];
    float r = 0.f, c = 0.f;
    for (int d = 0; d < DHEAD; d++) {
        float p = probe[bh*DHEAD + d];
        r += p * rowsum[((size_t)bh*DHEAD + d)*HC + t];
        c += p * colsum[((size_t)bh*DHEAD + d)*WC + t];
    }
    sr[t] = r; sc[t] = c;
    __syncthreads();
    if (t == 0) {
        bool used[64];
        for (int i = 0; i < 64; i++) used[i] = false;
        for (int i = 0; i < 8; i++) {
            float best = -1e38f; int bi = 0;
            for (int h = 0; h < 64; h++)
                if (!used[h] && sr[h] > best) { best = sr[h]; bi = h; }
            used[bi] = true; th[i] = bi;
        }
        for (int i = 0; i < 64; i++) used[i] = false;
        for (int i = 0; i < 8; i++) {
            float best = -1e38f; int bi = 0;
            for (int w = 0; w < 64; w++)
                if (!used[w] && sc[w] > best) { best = sc[w]; bi = w; }
            used[bi] = true; tw[i] = bi;
        }
        for (int i = 0; i < 8; i++)
            for (int j = 0; j < 8; j++)
                topidx[bh*NKV + i*8 + j] = th[i]*WC + tw[j];
    }
}

// ---------------- pack: K split [j][d] (pre-normalized); V at pruned px split [d][j] ----------------
__global__ void pack_k(const float* __restrict__ k,
                       const float* __restrict__ ctx_raw, const float2* __restrict__ cstat,
                       const float* __restrict__ cg, const float* __restrict__ cb_,
                       const float* __restrict__ wkv, const int* __restrict__ topidx,
                       __nv_bfloat16* __restrict__ kh, __nv_bfloat16* __restrict__ kl,
                       __nv_bfloat16* __restrict__ vh, __nv_bfloat16* __restrict__ vl) {
    extern __shared__ float ctx_s[];   // [c][j]
    __shared__ int pos[NKV];
    __shared__ float2 stj[NKV];
    int bh = blockIdx.x, b = bh >> 3, h = bh & 7;
    int tid = threadIdx.x;
    if (tid < NKV) {
        int p = topidx[bh*NKV + tid];
        pos[tid] = p;
        stj[tid] = cstat[(size_t)b*CPIX + p];
    }
    __syncthreads();

    int j = tid & 63, c0 = tid >> 6;
    float2 st = stj[j];
    for (int cc = 0; cc < 64; cc++) {
        int c = cc*4 + c0;
        float raw = ctx_raw[((size_t)b*CDIM + c)*CPIX + pos[j]];
        ctx_s[c*64 + j] = (raw - st.x)*st.y*cg[c] + cb_[c];
    }

    #pragma unroll
    for (int i = 0; i < 16; i++) {
        int idx = tid + i*256;
        int jj = idx >> 6, d = idx & 63;
        float kv = k[((size_t)bh*DHEAD + d)*CPIX + pos[jj]];
        __nv_bfloat16 hh, ll;
        split1(kv, hh, ll);
        kh[(size_t)bh*NKV*DHEAD + idx] = hh;
        kl[(size_t)bh*NKV*DHEAD + idx] = ll;
    }
    __syncthreads();

    for (int dd = 0; dd < 16; dd++) {
        int d = dd*4 + c0;
        const float* wr = wkv + ((size_t)(INNER + h*DHEAD + d))*CDIM;
        float acc = 0.f;
        #pragma unroll 8
        for (int c = 0; c < CDIM; c++) acc += wr[c] * ctx_s[c*64 + j];
        __nv_bfloat16 hh, ll;
        split1(acc, hh, ll);
        vh[(size_t)bh*NKV*DHEAD + d*64 + j] = hh;
        vl[(size_t)bh*NKV*DHEAD + d*64 + j] = ll;
    }
}

// ---------------- fused HMMA attention: in-register softmax (q pre-normalized) ----------------
#define AQ_TERM 18432                     // 128*RSB
#define AK_TERM 9216                      // 64*RSB
#define ATTN_SMEM (2*AQ_TERM + 2*AK_TERM)   // 55296
__global__ void __launch_bounds__(256)
attn_k(const float* __restrict__ qb_all,
       const __nv_bfloat16* __restrict__ kh_all, const __nv_bfloat16* __restrict__ kl_all,
       const __nv_bfloat16* __restrict__ vh_all, const __nv_bfloat16* __restrict__ vl_all,
       float* __restrict__ attno) {
    extern __shared__ char smem[];
    char* Qh = smem;                        // [px][RS]  (later Ph/Pl, then Os)
    char* Ql = smem + AQ_TERM;
    char* Kh = smem + 2*AQ_TERM;            // [j][RS] (later V [d][RS])
    char* Kl = smem + 2*AQ_TERM + AK_TERM;
    __shared__ float red[128][2];
    uint32_t qBase = smem_u32(Qh);
    uint32_t kBase = smem_u32(Kh);

    int bh = blockIdx.y;
    int px0 = blockIdx.x * 128;
    int tid = threadIdx.x, lane = tid & 31, wid = tid >> 5;
    int wm = wid & 3, wn = wid >> 2;
    int lr = lane >> 2, lc = lane & 3;

    const float* qb = qb_all + (size_t)bh*DHEAD*NPIX + px0;
    const uint32_t* khp = (const uint32_t*)(kh_all + (size_t)bh*NKV*DHEAD);
    const uint32_t* klp = (const uint32_t*)(kl_all + (size_t)bh*NKV*DHEAD);
    const uint32_t* vhp = (const uint32_t*)(vh_all + (size_t)bh*NKV*DHEAD);
    const uint32_t* vlp = (const uint32_t*)(vl_all + (size_t)bh*NKV*DHEAD);

    uint32_t aLane = (uint32_t)((wm*32 + ((lane>>3)&1)*8 + (lane&7))*RSB + (lane>>4)*16);
    uint32_t bLane = (uint32_t)(((lane>>4)*8 + (lane&7))*RSB + ((lane>>3)&1)*16 + wn*32*RSB);

    for (int i = tid; i < 2048; i += 256) {
        int j = i >> 5, dp = i & 31;
        ((uint32_t*)(Kh + j*RSB))[dp] = khp[i];
        ((uint32_t*)(Kl + j*RSB))[dp] = klp[i];
    }
    #pragma unroll
    for (int it = 0; it < 16; it++) {
        int idx = tid + it*256;
        int p  = (idx & 7) | (((idx >> 5) & 15) << 3);
        int dp = ((idx >> 3) & 3) | ((idx >> 9) << 2);
        float v0 = qb[(size_t)(2*dp)*NPIX + p];
        float v1 = qb[(size_t)(2*dp+1)*NPIX + p];
        uint32_t hi, lo;
        split2(v0, v1, hi, lo);
        ((uint32_t*)(Qh + p*RSB))[dp] = hi;
        ((uint32_t*)(Ql + p*RSB))[dp] = lo;
    }
    __syncthreads();

    // QK^T -> acc (registers)
    float acc[2][4][4];
    #pragma unroll
    for (int i = 0; i < 2; i++)
        #pragma unroll
        for (int j = 0; j < 4; j++)
            #pragma unroll
            for (int l = 0; l < 4; l++) acc[i][j][l] = 0.f;
    #pragma unroll
    for (int kk = 0; kk < 4; kk++) {
        uint32_t af[2][2][4], bfr[2][4][2];
        #pragma unroll
        for (int t = 0; t < 2; t++) {
            #pragma unroll
            for (int tm = 0; tm < 2; tm++)
                ldsm_x4(af[t][tm], qBase + t*AQ_TERM + tm*16*RSB + kk*32 + aLane);
            #pragma unroll
            for (int pr = 0; pr < 2; pr++) {
                uint32_t r[4];
                ldsm_x4(r, kBase + t*AK_TERM + pr*16*RSB + kk*32 + bLane);
                bfr[t][pr*2][0]   = r[0]; bfr[t][pr*2][1]   = r[1];
                bfr[t][pr*2+1][0] = r[2]; bfr[t][pr*2+1][1] = r[3];
            }
        }
        #pragma unroll
        for (int tm = 0; tm < 2; tm++)
            #pragma unroll
            for (int tn = 0; tn < 4; tn++) {
                mma_bf16(acc[tm][tn], af[0][tm], bfr[0][tn]);
                mma_bf16(acc[tm][tn], af[0][tm], bfr[1][tn]);
                mma_bf16(acc[tm][tn], af[1][tm], bfr[0][tn]);
            }
    }
    __syncthreads();

    // stage V into K region ([d][RS])
    for (int i = tid; i < 2048; i += 256) {
        int d = i >> 5, jp = i & 31;
        ((uint32_t*)(Kh + d*RSB))[jp] = vhp[i];
        ((uint32_t*)(Kl + d*RSB))[jp] = vlp[i];
    }

    // ---- in-register softmax over j ----
    float mrow[2][2];
    #pragma unroll
    for (int tm = 0; tm < 2; tm++) {
        float m0 = -1e30f, m1 = -1e30f;
        #pragma unroll
        for (int tn = 0; tn < 4; tn++) {
            m0 = fmaxf(m0, fmaxf(acc[tm][tn][0], acc[tm][tn][1]));
            m1 = fmaxf(m1, fmaxf(acc[tm][tn][2], acc[tm][tn][3]));
        }
        #pragma unroll
        for (int off = 1; off <= 2; off <<= 1) {
            m0 = fmaxf(m0, __shfl_xor_sync(~0u, m0, off));
            m1 = fmaxf(m1, __shfl_xor_sync(~0u, m1, off));
        }
        mrow[tm][0] = m0; mrow[tm][1] = m1;
    }
    if (lc == 0) {
        #pragma unroll
        for (int tm = 0; tm < 2; tm++) {
            red[wm*32 + tm*16 + lr][wn]     = mrow[tm][0];
            red[wm*32 + tm*16 + lr + 8][wn] = mrow[tm][1];
        }
    }
    __syncthreads();
    float fm[2][2];
    #pragma unroll
    for (int tm = 0; tm < 2; tm++) {
        fm[tm][0] = fmaxf(red[wm*32 + tm*16 + lr][0],     red[wm*32 + tm*16 + lr][1]);
        fm[tm][1] = fmaxf(red[wm*32 + tm*16 + lr + 8][0], red[wm*32 + tm*16 + lr + 8][1]);
    }
    __syncthreads();
    float srow[2][2] = {{0.f,0.f},{0.f,0.f}};
    #pragma unroll
    for (int tm = 0; tm < 2; tm++)
        #pragma unroll
        for (int tn = 0; tn < 4; tn++) {
            acc[tm][tn][0] = expf(acc[tm][tn][0] - fm[tm][0]);
            acc[tm][tn][1] = expf(acc[tm][tn][1] - fm[tm][0]);
            acc[tm][tn][2] = expf(acc[tm][tn][2] - fm[tm][1]);
            acc[tm][tn][3] = expf(acc[tm][tn][3] - fm[tm][1]);
            srow[tm][0] += acc[tm][tn][0] + acc[tm][tn][1];
            srow[tm][1] += acc[tm][tn][2] + acc[tm][tn][3];
        }
    #pragma unroll
    for (int tm = 0; tm < 2; tm++)
        #pragma unroll
        for (int off = 1; off <= 2; off <<= 1) {
            srow[tm][0] += __shfl_xor_sync(~0u, srow[tm][0], off);
            srow[tm][1] += __shfl_xor_sync(~0u, srow[tm][1], off);
        }
    if (lc == 0) {
        #pragma unroll
        for (int tm = 0; tm < 2; tm++) {
            red[wm*32 + tm*16 + lr][wn]     = srow[tm][0];
            red[wm*32 + tm*16 + lr + 8][wn] = srow[tm][1];
        }
    }
    __syncthreads();
    float fs[2][2];
    #pragma unroll
    for (int tm = 0; tm < 2; tm++) {
        fs[tm][0] = 1.f / (red[wm*32 + tm*16 + lr][0]     + red[wm*32 + tm*16 + lr][1]);
        fs[tm][1] = 1.f / (red[wm*32 + tm*16 + lr + 8][0] + red[wm*32 + tm*16 + lr + 8][1]);
    }

    // scale + split directly into Qh/Ql as P tiles [r][j]
    #pragma unroll
    for (int tm = 0; tm < 2; tm++)
        #pragma unroll
        for (int tn = 0; tn < 4; tn++) {
            int r1 = wm*32 + tm*16 + lr;
            int cw = wn*16 + tn*4 + lc;
            float p0 = acc[tm][tn][0] * fs[tm][0];
            float p1 = acc[tm][tn][1] * fs[tm][0];
            float p2 = acc[tm][tn][2] * fs[tm][1];
            float p3 = acc[tm][tn][3] * fs[tm][1];
            uint32_t hi, lo;
            split2(p0, p1, hi, lo);
            ((uint32_t*)(Qh + r1*RSB))[cw] = hi;
            ((uint32_t*)(Ql + r1*RSB))[cw] = lo;
            split2(p2, p3, hi, lo);
            ((uint32_t*)(Qh + (r1+8)*RSB))[cw] = hi;
            ((uint32_t*)(Ql + (r1+8)*RSB))[cw] = lo;
        }
    __syncthreads();

    // P @ V -> out[px][d]
    {
        float acc2[2][4][4];
        #pragma unroll
        for (int i = 0; i < 2; i++)
            #pragma unroll
            for (int j = 0; j < 4; j++)
                #pragma unroll
                for (int l = 0; l < 4; l++) acc2[i][j][l] = 0.f;
        #pragma unroll
        for (int kk = 0; kk < 4; kk++) {
            uint32_t af[2][2][4], bfr[2][4][2];
            #pragma unroll
            for (int t = 0; t < 2; t++) {
                #pragma unroll
                for (int tm = 0; tm < 2; tm++)
                    ldsm_x4(af[t][tm], qBase + t*AQ_TERM + tm*16*RSB + kk*32 + aLane);
                #pragma unroll
                for (int pr = 0; pr < 2; pr++) {
                    uint32_t r[4];
                    ldsm_x4(r, kBase + t*AK_TERM + pr*16*RSB + kk*32 + bLane);
                    bfr[t][pr*2][0]   = r[0]; bfr[t][pr*2][1]   = r[1];
                    bfr[t][pr*2+1][0] = r[2]; bfr[t][pr*2+1][1] = r[3];
                }
            }
            #pragma unroll
            for (int tm = 0; tm < 2; tm++)
                #pragma unroll
                for (int tn = 0; tn < 4; tn++) {
                    mma_bf16(acc2[tm][tn], af[0][tm], bfr[0][tn]);
                    mma_bf16(acc2[tm][tn], af[0][tm], bfr[1][tn]);
                    mma_bf16(acc2[tm][tn], af[1][tm], bfr[0][tn]);
                }
        }
        __syncthreads();
        float* Os = (float*)Qh;
        #pragma unroll
        for (int tm = 0; tm < 2; tm++)
            #pragma unroll
            for (int tn = 0; tn < 4; tn++) {
                int r = wm*32 + tm*16 + lr;
                int c = wn*32 + tn*8 + lc*2;
                Os[c*132 + r]       = acc2[tm][tn][0];
                Os[(c+1)*132 + r]   = acc2[tm][tn][1];
                Os[c*132 + r + 8]   = acc2[tm][tn][2];
                Os[(c+1)*132 + r+8] = acc2[tm][tn][3];
            }
        __syncthreads();
        float* ob = attno + (size_t)bh*DHEAD*NPIX + px0;
        for (int i = tid; i < 8192; i += 256) {
            int d = i >> 7, p = i & 127;
            ob[(size_t)d*NPIX + p] = Os[d*132 + p];
        }
    }
}

// ---------------- final single-pass: normalize(obuf) + residual ----------------
__global__ void final1_k(const float* __restrict__ x, const float2* __restrict__ st,
                         const float* __restrict__ g, const float* __restrict__ bb,
                         const float* __restrict__ gamma, const float* __restrict__ resid,
                         float* __restrict__ y) {
    int i = blockIdx.x*256 + threadIdx.x;
    int px4 = i % (NPIX/4);
    int rest = i / (NPIX/4);
    int c = rest % CDIM, b = rest / CDIM;
    const float4* stp = (const float4*)&st[(size_t)b*NPIX + px4*4];
    float4 s01 = stp[0], s23 = stp[1];
    float4 v  = ((const float4*)x)[i];
    float4 rr = ((const float4*)resid)[i];
    float gg = g[c], bv = bb[c], gm = gamma[0];
    float4 o;
    o.x = gm*((v.x - s01.x)*s01.y*gg + bv) + rr.x;
    o.y = gm*((v.y - s01.z)*s01.w*gg + bv) + rr.y;
    o.z = gm*((v.z - s23.x)*s23.y*gg + bv) + rr.z;
    o.w = gm*((v.w - s23.z)*s23.w*gg + bv) + rr.w;
    ((float4*)y)[i] = o;
}

// ---------------- launch ----------------
extern "C" void kernel_launch(void* const* d_in, const int* in_sizes, int n_in,
                              void* d_out, int out_size) {
    const float* query_source = (const float*)d_in[0];
    const float* context      = (const float*)d_in[1];
    const float* qs_g  = (const float*)d_in[2];
    const float* qs_b  = (const float*)d_in[3];
    const float* ctx_g = (const float*)d_in[4];
    const float* ctx_b = (const float*)d_in[5];
    const float* out_g = (const float*)d_in[6];
    const float* out_b = (const float*)d_in[7];
    const float* w_q   = (const float*)d_in[8];
    const float* w_kv  = (const float*)d_in[9];
    const float* w_out = (const float*)d_in[10];
    const float* gamma = (const float*)d_in[11];
    float* out = (float*)d_out;

    float *qb, *kb, *attno, *obuf, *ppart, *probe, *rowsum, *colsum;
    int* topidx;
    float2 *cstat, *qstat, *opart, *ostat;
    __nv_bfloat16 *kh, *kl, *vh, *vl, *wqh, *wql, *wkh, *wkl, *woh, *wol;
    cudaGetSymbolAddress((void**)&qb,    g_q);
    cudaGetSymbolAddress((void**)&kb,    g_k);
    cudaGetSymbolAddress((void**)&attno, g_attno);
    cudaGetSymbolAddress((void**)&obuf,  g_obuf);
    cudaGetSymbolAddress((void**)&ppart, g_probe_part);
    cudaGetSymbolAddress((void**)&probe, g_probe);
    cudaGetSymbolAddress((void**)&rowsum,g_rowsum);
    cudaGetSymbolAddress((void**)&colsum,g_colsum);
    cudaGetSymbolAddress((void**)&topidx,g_topidx);
    cudaGetSymbolAddress((void**)&cstat, g_ctx_stat);
    cudaGetSymbolAddress((void**)&qstat, g_qs_stat);
    cudaGetSymbolAddress((void**)&opart, g_opart);
    cudaGetSymbolAddress((void**)&ostat, g_ostat);
    cudaGetSymbolAddress((void**)&kh,    g_kh);
    cudaGetSymbolAddress((void**)&kl,    g_kl);
    cudaGetSymbolAddress((void**)&vh,    g_vh);
    cudaGetSymbolAddress((void**)&vl,    g_vl);
    cudaGetSymbolAddress((void**)&wqh,   g_wq_h);
    cudaGetSymbolAddress((void**)&wql,   g_wq_l);
    cudaGetSymbolAddress((void**)&wkh,   g_wk_h);
    cudaGetSymbolAddress((void**)&wkl,   g_wk_l);
    cudaGetSymbolAddress((void**)&woh,   g_wo_h);
    cudaGetSymbolAddress((void**)&wol,   g_wo_l);

    cudaFuncSetAttribute(proj_gemm_k, cudaFuncAttributeMaxDynamicSharedMemorySize, GEMM_SMEM);
    cudaFuncSetAttribute(hmma_gemm_k, cudaFuncAttributeMaxDynamicSharedMemorySize, GEMM_SMEM);
    cudaFuncSetAttribute(attn_k, cudaFuncAttributeMaxDynamicSharedMemorySize, ATTN_SMEM);
    cudaFuncSetAttribute(pack_k, cudaFuncAttributeMaxDynamicSharedMemorySize, 256*64*4);

    // 0) weight splits (tiny)
    split_w_k<<<(INNER*CDIM/4 + 255)/256, 256>>>(w_q,   wqh, wql, INNER*CDIM);
    split_w_k<<<(INNER*CDIM/4 + 255)/256, 256>>>(w_kv,  wkh, wkl, INNER*CDIM);  // K half
    split_w_k<<<(CDIM*INNER/4 + 255)/256, 256>>>(w_out, woh, wol, CDIM*INNER);

    // 1) per-pixel layernorm stats
    stat_k<<<dim3(CPIX/128, BATCH), 256>>>(context, cstat, CPIX);
    stat_k<<<dim3(NPIX/128, BATCH), 256>>>(query_source, qstat, NPIX);

    // 2) combined q+k projection (fused norm, L2-normalized outputs, probe partials)
    proj_gemm_k<<<dim3(NKT + NPB, INNER/128, BATCH), 256, GEMM_SMEM>>>(
        wkh, wkl, wqh, wql, context, query_source, cstat, qstat,
        ctx_g, ctx_b, qs_g, qs_b, kb, qb, ppart);

    // 3) probe + pruning scores
    probe_reduce_k<<<BH, DHEAD>>>(ppart, probe);
    rowcol_k<<<dim3(DHEAD, BH), 64>>>(kb, rowsum, colsum);
    topk_k<<<BH, 64>>>(probe, rowsum, colsum, topidx);

    // 4) pack pruned K (split) + compute pruned V (split, transposed)
    pack_k<<<BH, 256, 256*64*4>>>(kb, context, cstat, ctx_g, ctx_b,
                                  w_kv, topidx, kh, kl, vh, vl);

    // 5) fused HMMA attention (q pre-normalized)
    attn_k<<<dim3(NPIX/128, BH), 256, ATTN_SMEM>>>(qb, kh, kl, vh, vl, attno);

    // 6) output projection with fused per-pixel sum/sumsq epilogue
    hmma_gemm_k<<<dim3(NPIX/64, CDIM/128, BATCH), 256, GEMM_SMEM>>>(
        woh, wol, attno, obuf, CDIM, NPIX, INNER,
        (long)INNER*NPIX, (long)CDIM*NPIX, (float*)opart);

    // 6b) combine partials -> per-pixel (mean, rstd)
    ostat_k<<<(BATCH*NPIX)/256, 256>>>(opart, ostat);

    // 7) final single-pass norm + gamma + residual
    final1_k<<<(BATCH*CDIM*NPIX/4)/256, 256>>>(obuf, ostat, out_g, out_b, gamma,
                                               query_source, out);
}